// round 3
// baseline (speedup 1.0000x reference)
#include <cuda_runtime.h>

// ---------------------------------------------------------------------------
// H2GCN forward, fp32 baseline.
// edge_index is read as int32 (JAX default no-x64 makes it int32 despite the
// reference saying int64); a runtime probe handles the int64 case too.
// ---------------------------------------------------------------------------

#define NN   100000
#define EE   800000
#define INF_ 512
#define HF   64
#define CF   40
#define ZF   320   // 5 * HF concat width

// ---- scratch (static device globals; no allocation anywhere) ----
__device__ float g_deg[NN];
__device__ float g_dinv[NN];
__device__ float g_diag2[NN];
__device__ int   g_rowptr[NN + 1];
__device__ int   g_cursor[NN];
__device__ int   g_adj[2 * EE];
__device__ float g_z[(size_t)NN * ZF];    // [node][5*64] chunks: h,h1a,h2a,h1b,h2b
__device__ float g_curB[(size_t)NN * HF]; // cur = h1a + h2a
__device__ float g_hid[(size_t)NN * HF];  // hidden layer
__device__ float g_sum[HF];
__device__ float g_sumsq[HF];
__device__ float g_bnA[HF];
__device__ float g_bnB[HF];
__device__ int   g_is64;

// ---------------------------------------------------------------------------
// dtype probe: int64 little-endian values < 2^31 -> every odd int32 word == 0
__global__ void k_detect(const int* __restrict__ ei32) {
    int oddzero = 1;
#pragma unroll
    for (int i = 1; i < 16; i += 2)
        if (ei32[i] != 0) oddzero = 0;
    g_is64 = oddzero;
}

__device__ __forceinline__ void load_edge(const int* __restrict__ ei32, int e,
                                          int& u, int& v) {
    if (g_is64) {
        u = ei32[2 * e];             // low word of row0 elem e
        v = ei32[2 * EE + 2 * e];    // low word of row1 elem e
    } else {
        u = ei32[e];
        v = ei32[EE + e];
    }
}

// ---------------------------------------------------------------------------
__global__ void k_init() {
    int i = blockIdx.x * blockDim.x + threadIdx.x;
    int stride = gridDim.x * blockDim.x;
    for (int j = i; j < NN; j += stride) {
        g_deg[j] = 0.f;
        g_diag2[j] = 0.f;
        g_cursor[j] = 0;
    }
    if (i < HF) { g_sum[i] = 0.f; g_sumsq[i] = 0.f; }
}

__global__ void k_deg(const int* __restrict__ ei32) {
    int e = blockIdx.x * blockDim.x + threadIdx.x;
    if (e >= EE) return;
    int u, v;
    load_edge(ei32, e, u, v);
    if ((unsigned)u >= NN || (unsigned)v >= NN || u == v) return;
    atomicAdd(g_deg + u, 1.f);
    atomicAdd(g_deg + v, 1.f);
}

__global__ void k_dinv() {
    int i = blockIdx.x * blockDim.x + threadIdx.x;
    if (i < NN) {
        float d = g_deg[i];
        g_dinv[i] = (d > 0.f) ? rsqrtf(d) : 0.f;
    }
}

// single-block exclusive scan of (int)g_deg -> g_rowptr, 8 elems/thread
__global__ void k_scan() {
    __shared__ int ssum[1024];
    __shared__ int s_carry;
    int tid = threadIdx.x;
    if (tid == 0) s_carry = 0;
    __syncthreads();
    const int TILE = 1024 * 8;
    for (int base = 0; base < NN; base += TILE) {
        int vals[8];
        int local = 0;
        int i0 = base + tid * 8;
#pragma unroll
        for (int q = 0; q < 8; q++) {
            int i = i0 + q;
            int v = (i < NN) ? (int)g_deg[i] : 0;
            vals[q] = local;
            local += v;
        }
        ssum[tid] = local;
        __syncthreads();
        for (int off = 1; off < 1024; off <<= 1) {
            int t = (tid >= off) ? ssum[tid - off] : 0;
            __syncthreads();
            ssum[tid] += t;
            __syncthreads();
        }
        int total = ssum[1023];
        int texcl = s_carry + ssum[tid] - local;
#pragma unroll
        for (int q = 0; q < 8; q++) {
            int i = i0 + q;
            if (i < NN) g_rowptr[i] = texcl + vals[q];
        }
        __syncthreads();
        if (tid == 0) s_carry += total;
        __syncthreads();
    }
    if (tid == 0) g_rowptr[NN] = s_carry;
}

__global__ void k_fill(const int* __restrict__ ei32) {
    int e = blockIdx.x * blockDim.x + threadIdx.x;
    if (e >= EE) return;
    int u, v;
    load_edge(ei32, e, u, v);
    if ((unsigned)u >= NN || (unsigned)v >= NN || u == v) return;
    float w = g_dinv[u] * g_dinv[v];
    float ww = w * w;
    atomicAdd(g_diag2 + u, ww);
    atomicAdd(g_diag2 + v, ww);
    int p = atomicAdd(g_cursor + u, 1);
    g_adj[g_rowptr[u] + p] = v;
    int q = atomicAdd(g_cursor + v, 1);
    g_adj[g_rowptr[v] + q] = u;
}

// ---------------------------------------------------------------------------
// Generic tiled SGEMM: C[M x Nc] = act(A[M x K] @ B[Nc x K]^T + bias)
// BM=64, BN=64 (covers Nc<=64), BK=32, 256 threads, 4x4 per thread.
// aSel: 0=Ain param, 1=g_z, 2=g_hid.  cSel: 0=Cout param, 1=g_z, 2=g_hid.
// ---------------------------------------------------------------------------
__global__ void k_sgemm(const float* __restrict__ Ain, int M, int K, int lda,
                        const float* __restrict__ B, int Nc, int ldb,
                        const float* __restrict__ bias,
                        float* __restrict__ Cout, int ldc, int doRelu,
                        int aSel, int cSel) {
    const float* A = (aSel == 1) ? g_z : (aSel == 2) ? g_hid : Ain;
    float* C = (cSel == 1) ? g_z : (cSel == 2) ? g_hid : Cout;

    __shared__ float As[32 * 64];
    __shared__ float Bs[32 * 64];
    int t = threadIdx.x;
    int tr = t >> 4;       // 0..15 -> rows tr*4..tr*4+3
    int tc = t & 15;       // 0..15 -> cols tc*4..tc*4+3
    int row0 = blockIdx.x * 64;

    float acc[4][4];
#pragma unroll
    for (int i = 0; i < 4; i++)
#pragma unroll
        for (int j = 0; j < 4; j++) acc[i][j] = 0.f;

    for (int k0 = 0; k0 < K; k0 += 32) {
#pragma unroll
        for (int l = 0; l < 2; l++) {
            int id = t + l * 256;      // 0..511
            int r  = id >> 3;          // 0..63
            int c4 = id & 7;           // 0..7 (float4 within 32 k's)
            float4 va = make_float4(0.f, 0.f, 0.f, 0.f);
            int gr = row0 + r;
            if (gr < M)
                va = *reinterpret_cast<const float4*>(A + (size_t)gr * lda + k0 + c4 * 4);
            As[(c4 * 4 + 0) * 64 + r] = va.x;
            As[(c4 * 4 + 1) * 64 + r] = va.y;
            As[(c4 * 4 + 2) * 64 + r] = va.z;
            As[(c4 * 4 + 3) * 64 + r] = va.w;
            float4 vb = make_float4(0.f, 0.f, 0.f, 0.f);
            if (r < Nc)
                vb = *reinterpret_cast<const float4*>(B + (size_t)r * ldb + k0 + c4 * 4);
            Bs[(c4 * 4 + 0) * 64 + r] = vb.x;
            Bs[(c4 * 4 + 1) * 64 + r] = vb.y;
            Bs[(c4 * 4 + 2) * 64 + r] = vb.z;
            Bs[(c4 * 4 + 3) * 64 + r] = vb.w;
        }
        __syncthreads();
#pragma unroll
        for (int k = 0; k < 32; k++) {
            float4 a4 = *reinterpret_cast<const float4*>(&As[k * 64 + tr * 4]);
            float4 b4 = *reinterpret_cast<const float4*>(&Bs[k * 64 + tc * 4]);
            float av[4] = {a4.x, a4.y, a4.z, a4.w};
            float bv[4] = {b4.x, b4.y, b4.z, b4.w};
#pragma unroll
            for (int i = 0; i < 4; i++)
#pragma unroll
                for (int j = 0; j < 4; j++)
                    acc[i][j] += av[i] * bv[j];
        }
        __syncthreads();
    }

#pragma unroll
    for (int i = 0; i < 4; i++) {
        int R = row0 + tr * 4 + i;
        if (R >= M) continue;
#pragma unroll
        for (int j = 0; j < 4; j++) {
            int Cc = tc * 4 + j;
            if (Cc >= Nc) continue;
            float v = acc[i][j] + bias[Cc];
            if (doRelu) v = fmaxf(v, 0.f);
            C[(size_t)R * ldc + Cc] = v;
        }
    }
}

// ---------------------------------------------------------------------------
// BN stats over g_z chunk 0 (stride ZF)
// ---------------------------------------------------------------------------
__global__ void k_stats() {
    int f = threadIdx.x & 63;
    int slot = threadIdx.x >> 6;  // 0..3
    float s = 0.f, s2 = 0.f;
    for (int i = blockIdx.x * 4 + slot; i < NN; i += gridDim.x * 4) {
        float v = g_z[(size_t)i * ZF + f];
        s += v;
        s2 += v * v;
    }
    __shared__ float sh[2][4][64];
    sh[0][slot][f] = s;
    sh[1][slot][f] = s2;
    __syncthreads();
    if (slot == 0) {
        float ts = sh[0][0][f] + sh[0][1][f] + sh[0][2][f] + sh[0][3][f];
        float t2 = sh[1][0][f] + sh[1][1][f] + sh[1][2][f] + sh[1][3][f];
        atomicAdd(g_sum + f, ts);
        atomicAdd(g_sumsq + f, t2);
    }
}

__global__ void k_bnfin(const float* __restrict__ gamma, const float* __restrict__ beta) {
    int f = threadIdx.x;
    float mu = g_sum[f] / (float)NN;
    float var = g_sumsq[f] / (float)NN - mu * mu;
    float inv = rsqrtf(var + 1e-5f);
    float sc = gamma[f] * inv;
    g_bnA[f] = sc;
    g_bnB[f] = beta[f] - mu * sc;
}

__global__ void k_bnapply() {
    int i = blockIdx.x * blockDim.x + threadIdx.x;
    if (i >= NN * HF) return;
    int node = i >> 6, f = i & 63;
    size_t idx = (size_t)node * ZF + f;
    g_z[idx] = g_z[idx] * g_bnA[f] + g_bnB[f];
}

// ---------------------------------------------------------------------------
// SpMM: dst[u] = dinv[u] * sum_{v in adj(u)} dinv[v] * src[v]  (- diag2[u]*prev[u])
// warp per node, 2 features per lane (float2).
// srcInZ: 1 -> src = g_z + srcOff (stride ZF), 0 -> src = g_curB (stride HF)
// prevMode: 0=none, 1=prev in g_z at prevOff (stride ZF), 2=prev = g_curB (stride HF)
// dst always g_z + dstOff (stride ZF). writeCur: also store src+dst into g_curB.
// ---------------------------------------------------------------------------
__global__ void k_spmm(int srcInZ, int srcOff, int prevMode, int prevOff,
                       int dstOff, int writeCur) {
    int node = blockIdx.x * 4 + (threadIdx.x >> 5);
    if (node >= NN) return;
    int lane = threadIdx.x & 31;

    const float* src = srcInZ ? (g_z + srcOff) : g_curB;
    int sld = srcInZ ? ZF : HF;

    int s = g_rowptr[node];
    int e = g_rowptr[node + 1];
    float ax = 0.f, ay = 0.f;
#pragma unroll 4
    for (int j = s; j < e; j++) {
        int v = g_adj[j];
        float dv = g_dinv[v];
        float2 xv = *reinterpret_cast<const float2*>(src + (size_t)v * sld + 2 * lane);
        ax += dv * xv.x;
        ay += dv * xv.y;
    }
    float du = g_dinv[node];
    ax *= du;
    ay *= du;
    if (prevMode) {
        const float* prev = (prevMode == 1) ? (g_z + prevOff) : g_curB;
        int pld = (prevMode == 1) ? ZF : HF;
        float d2 = g_diag2[node];
        float2 p = *reinterpret_cast<const float2*>(prev + (size_t)node * pld + 2 * lane);
        ax -= d2 * p.x;
        ay -= d2 * p.y;
    }
    *reinterpret_cast<float2*>(g_z + dstOff + (size_t)node * ZF + 2 * lane) =
        make_float2(ax, ay);
    if (writeCur) {
        float2 sown = *reinterpret_cast<const float2*>(src + (size_t)node * sld + 2 * lane);
        *reinterpret_cast<float2*>(g_curB + (size_t)node * HF + 2 * lane) =
            make_float2(sown.x + ax, sown.y + ay);
    }
}

// ---------------------------------------------------------------------------
extern "C" void kernel_launch(void* const* d_in, const int* in_sizes, int n_in,
                              void* d_out, int out_size) {
    const float* x       = (const float*)d_in[0];
    const int*   ei32    = (const int*)d_in[1];   // int32 (JAX no-x64); probe handles int64
    const float* b_embed = (const float*)d_in[3];
    const float* bn_g    = (const float*)d_in[4];
    const float* bn_b    = (const float*)d_in[5];
    const float* W_embed = (const float*)d_in[2];
    const float* W1      = (const float*)d_in[6];
    const float* b1      = (const float*)d_in[7];
    const float* W2      = (const float*)d_in[8];
    const float* b2      = (const float*)d_in[9];
    float* out = (float*)d_out;

    // graph prep
    k_detect<<<1, 1>>>(ei32);
    k_init<<<256, 256>>>();
    k_deg<<<(EE + 255) / 256, 256>>>(ei32);
    k_dinv<<<(NN + 255) / 256, 256>>>();
    k_scan<<<1, 1024>>>();
    k_fill<<<(EE + 255) / 256, 256>>>(ei32);

    // embed: g_z chunk0 = relu(x @ W_embed^T + b_embed)
    k_sgemm<<<(NN + 63) / 64, 256>>>(x, NN, INF_, INF_, W_embed, HF, INF_, b_embed,
                                     nullptr, ZF, 1, /*aSel*/0, /*cSel*/1);
    // batchnorm (training stats)
    k_stats<<<256, 256>>>();
    k_bnfin<<<1, 64>>>(bn_g, bn_b);
    k_bnapply<<<(NN * HF + 255) / 256, 256>>>();

    int spmm_grid = (NN + 3) / 4;
    // hop 1: h1a = A h ; h2a = A h1a - diag2*h ; curB = h1a + h2a
    k_spmm<<<spmm_grid, 128>>>(1, 0 * HF, 0, 0, 1 * HF, 0);
    k_spmm<<<spmm_grid, 128>>>(1, 1 * HF, 1, 0 * HF, 2 * HF, 1);
    // hop 2: h1b = A curB ; h2b = A h1b - diag2*curB
    k_spmm<<<spmm_grid, 128>>>(0, 0, 0, 0, 3 * HF, 0);
    k_spmm<<<spmm_grid, 128>>>(1, 3 * HF, 2, 0, 4 * HF, 0);

    // MLP: hid = relu(z @ W1^T + b1); out = hid @ W2^T + b2
    k_sgemm<<<(NN + 63) / 64, 256>>>(nullptr, NN, ZF, ZF, W1, HF, ZF, b1,
                                     nullptr, HF, 1, /*aSel*/1, /*cSel*/2);
    k_sgemm<<<(NN + 63) / 64, 256>>>(nullptr, NN, HF, HF, W2, CF, HF, b2,
                                     out, CF, 0, /*aSel*/2, /*cSel*/0);
}

// round 4
// speedup vs baseline: 1.4631x; 1.4631x over previous
#include <cuda_runtime.h>

// ---------------------------------------------------------------------------
// H2GCN forward. GEMMs on tf32 tensor cores (mma.sync.m16n8k8), fp32 accum.
// ---------------------------------------------------------------------------

#define NN   100000
#define EE   800000
#define INF_ 512
#define HF   64
#define CF   40
#define ZF   320   // 5 * HF concat width

// ---- scratch (static device globals; no allocation anywhere) ----
__device__ float g_deg[NN];
__device__ float g_dinv[NN];
__device__ float g_diag2[NN];
__device__ int   g_rowptr[NN + 1];
__device__ int   g_cursor[NN];
__device__ int   g_adj[2 * EE];
__device__ float g_z[(size_t)NN * ZF];    // [node][5*64] chunks: h,h1a,h2a,h1b,h2b
__device__ float g_curB[(size_t)NN * HF]; // cur = h1a + h2a
__device__ float g_hid[(size_t)NN * HF];  // hidden layer
__device__ float g_sum[HF];
__device__ float g_sumsq[HF];
__device__ float g_bnA[HF];
__device__ float g_bnB[HF];
__device__ int   g_is64;

// ---------------------------------------------------------------------------
// dtype probe: int64 little-endian values < 2^31 -> every odd int32 word == 0
__global__ void k_detect(const int* __restrict__ ei32) {
    int oddzero = 1;
#pragma unroll
    for (int i = 1; i < 16; i += 2)
        if (ei32[i] != 0) oddzero = 0;
    g_is64 = oddzero;
}

__device__ __forceinline__ void load_edge(const int* __restrict__ ei32, int e,
                                          int& u, int& v) {
    if (g_is64) {
        u = ei32[2 * e];
        v = ei32[2 * EE + 2 * e];
    } else {
        u = ei32[e];
        v = ei32[EE + e];
    }
}

// ---------------------------------------------------------------------------
__global__ void k_init() {
    int i = blockIdx.x * blockDim.x + threadIdx.x;
    int stride = gridDim.x * blockDim.x;
    for (int j = i; j < NN; j += stride) {
        g_deg[j] = 0.f;
        g_diag2[j] = 0.f;
        g_cursor[j] = 0;
    }
    if (i < HF) { g_sum[i] = 0.f; g_sumsq[i] = 0.f; }
}

__global__ void k_deg(const int* __restrict__ ei32) {
    int e = blockIdx.x * blockDim.x + threadIdx.x;
    if (e >= EE) return;
    int u, v;
    load_edge(ei32, e, u, v);
    if ((unsigned)u >= NN || (unsigned)v >= NN || u == v) return;
    atomicAdd(g_deg + u, 1.f);
    atomicAdd(g_deg + v, 1.f);
}

__global__ void k_dinv() {
    int i = blockIdx.x * blockDim.x + threadIdx.x;
    if (i < NN) {
        float d = g_deg[i];
        g_dinv[i] = (d > 0.f) ? rsqrtf(d) : 0.f;
    }
}

// single-block exclusive scan of (int)g_deg -> g_rowptr, 8 elems/thread
__global__ void k_scan() {
    __shared__ int ssum[1024];
    __shared__ int s_carry;
    int tid = threadIdx.x;
    if (tid == 0) s_carry = 0;
    __syncthreads();
    const int TILE = 1024 * 8;
    for (int base = 0; base < NN; base += TILE) {
        int vals[8];
        int local = 0;
        int i0 = base + tid * 8;
#pragma unroll
        for (int q = 0; q < 8; q++) {
            int i = i0 + q;
            int v = (i < NN) ? (int)g_deg[i] : 0;
            vals[q] = local;
            local += v;
        }
        ssum[tid] = local;
        __syncthreads();
        for (int off = 1; off < 1024; off <<= 1) {
            int t = (tid >= off) ? ssum[tid - off] : 0;
            __syncthreads();
            ssum[tid] += t;
            __syncthreads();
        }
        int total = ssum[1023];
        int texcl = s_carry + ssum[tid] - local;
#pragma unroll
        for (int q = 0; q < 8; q++) {
            int i = i0 + q;
            if (i < NN) g_rowptr[i] = texcl + vals[q];
        }
        __syncthreads();
        if (tid == 0) s_carry += total;
        __syncthreads();
    }
    if (tid == 0) g_rowptr[NN] = s_carry;
}

__global__ void k_fill(const int* __restrict__ ei32) {
    int e = blockIdx.x * blockDim.x + threadIdx.x;
    if (e >= EE) return;
    int u, v;
    load_edge(ei32, e, u, v);
    if ((unsigned)u >= NN || (unsigned)v >= NN || u == v) return;
    float w = g_dinv[u] * g_dinv[v];
    float ww = w * w;
    atomicAdd(g_diag2 + u, ww);
    atomicAdd(g_diag2 + v, ww);
    int p = atomicAdd(g_cursor + u, 1);
    g_adj[g_rowptr[u] + p] = v;
    int q = atomicAdd(g_cursor + v, 1);
    g_adj[g_rowptr[v] + q] = u;
}

// ---------------------------------------------------------------------------
// tf32 tensor-core GEMM: C[M x Nc] = act(A[M x K] @ B[Nc x K]^T + bias)
// BM=128, BN=64, BK=16, 256 threads, warp tile 32x32 (mma m16n8k8).
// Requires K % 16 == 0, lda/ldb % 4 == 0, Nc even, Nc <= 64.
// aSel: 0=Ain param, 1=g_z, 2=g_hid.  cSel: 0=Cout param, 1=g_z, 2=g_hid.
// ---------------------------------------------------------------------------
__device__ __forceinline__ unsigned f2tf(float f) {
    unsigned r;
    asm("cvt.rna.tf32.f32 %0, %1;" : "=r"(r) : "f"(f));
    return r;
}

#define SAS 36  // shared stride in floats: 36*r mod 32 = 4r -> conflict-free frags

__global__ void k_mma(const float* __restrict__ Ain, int M, int K, int lda,
                      const float* __restrict__ B, int Nc, int ldb,
                      const float* __restrict__ bias,
                      float* __restrict__ Cout, int ldc, int doRelu,
                      int aSel, int cSel) {
    const float* A = (aSel == 1) ? g_z : (aSel == 2) ? g_hid : Ain;
    float* C = (cSel == 1) ? g_z : (cSel == 2) ? g_hid : Cout;

    __shared__ unsigned As[128 * SAS];
    __shared__ unsigned Bs[64 * SAS];

    int t = threadIdx.x;
    int w = t >> 5, lane = t & 31;
    int g = lane >> 2, tig = lane & 3;
    int wm = (w & 3) * 32;     // warp m origin in tile
    int wn = (w >> 2) * 32;    // warp n origin in tile
    int row0 = blockIdx.x * 128;

    float acc[2][4][4];
#pragma unroll
    for (int im = 0; im < 2; im++)
#pragma unroll
        for (int in = 0; in < 4; in++)
#pragma unroll
            for (int q = 0; q < 4; q++) acc[im][in][q] = 0.f;

    int ar = t >> 1;                 // A row this thread loads (0..127)
    int abase = (t & 1) * 2;         // chunk pair 0/2
    int br = t >> 2, bc4 = t & 3;    // B row / chunk

    for (int k0 = 0; k0 < K; k0 += 16) {
#pragma unroll
        for (int j = 0; j < 2; j++) {
            int c4 = abase + j;
            float4 v = make_float4(0.f, 0.f, 0.f, 0.f);
            int gr = row0 + ar;
            if (gr < M)
                v = *reinterpret_cast<const float4*>(A + (size_t)gr * lda + k0 + c4 * 4);
            unsigned* d = &As[ar * SAS + c4 * 4];
            d[0] = f2tf(v.x); d[1] = f2tf(v.y); d[2] = f2tf(v.z); d[3] = f2tf(v.w);
        }
        {
            float4 v = make_float4(0.f, 0.f, 0.f, 0.f);
            if (br < Nc)
                v = *reinterpret_cast<const float4*>(B + (size_t)br * ldb + k0 + bc4 * 4);
            unsigned* d = &Bs[br * SAS + bc4 * 4];
            d[0] = f2tf(v.x); d[1] = f2tf(v.y); d[2] = f2tf(v.z); d[3] = f2tf(v.w);
        }
        __syncthreads();

#pragma unroll
        for (int ks = 0; ks < 2; ks++) {
            int kb = ks * 8;
            unsigned a[2][4];
#pragma unroll
            for (int im = 0; im < 2; im++) {
                int r = wm + im * 16;
                a[im][0] = As[(r + g) * SAS + kb + tig];
                a[im][1] = As[(r + g + 8) * SAS + kb + tig];
                a[im][2] = As[(r + g) * SAS + kb + tig + 4];
                a[im][3] = As[(r + g + 8) * SAS + kb + tig + 4];
            }
            unsigned b[4][2];
#pragma unroll
            for (int in = 0; in < 4; in++) {
                int c = wn + in * 8;
                b[in][0] = Bs[(c + g) * SAS + kb + tig];
                b[in][1] = Bs[(c + g) * SAS + kb + tig + 4];
            }
#pragma unroll
            for (int im = 0; im < 2; im++)
#pragma unroll
                for (int in = 0; in < 4; in++) {
                    asm volatile(
                        "mma.sync.aligned.m16n8k8.row.col.f32.tf32.tf32.f32 "
                        "{%0,%1,%2,%3}, {%4,%5,%6,%7}, {%8,%9}, {%0,%1,%2,%3};"
                        : "+f"(acc[im][in][0]), "+f"(acc[im][in][1]),
                          "+f"(acc[im][in][2]), "+f"(acc[im][in][3])
                        : "r"(a[im][0]), "r"(a[im][1]), "r"(a[im][2]), "r"(a[im][3]),
                          "r"(b[in][0]), "r"(b[in][1]));
                }
        }
        __syncthreads();
    }

    // epilogue
#pragma unroll
    for (int im = 0; im < 2; im++) {
#pragma unroll
        for (int in = 0; in < 4; in++) {
            int Cc = wn + in * 8 + 2 * tig;
            if (Cc >= Nc) continue;
            float bx = bias[Cc], by = bias[Cc + 1];
            int R0 = row0 + wm + im * 16 + g;
            float v0 = acc[im][in][0] + bx;
            float v1 = acc[im][in][1] + by;
            float v2 = acc[im][in][2] + bx;
            float v3 = acc[im][in][3] + by;
            if (doRelu) {
                v0 = fmaxf(v0, 0.f); v1 = fmaxf(v1, 0.f);
                v2 = fmaxf(v2, 0.f); v3 = fmaxf(v3, 0.f);
            }
            if (R0 < M)
                *reinterpret_cast<float2*>(C + (size_t)R0 * ldc + Cc) = make_float2(v0, v1);
            if (R0 + 8 < M)
                *reinterpret_cast<float2*>(C + (size_t)(R0 + 8) * ldc + Cc) = make_float2(v2, v3);
        }
    }
}

// ---------------------------------------------------------------------------
// BN stats over g_z chunk 0 (stride ZF)
// ---------------------------------------------------------------------------
__global__ void k_stats() {
    int f = threadIdx.x & 63;
    int slot = threadIdx.x >> 6;  // 0..3
    float s = 0.f, s2 = 0.f;
    for (int i = blockIdx.x * 4 + slot; i < NN; i += gridDim.x * 4) {
        float v = g_z[(size_t)i * ZF + f];
        s += v;
        s2 += v * v;
    }
    __shared__ float sh[2][4][64];
    sh[0][slot][f] = s;
    sh[1][slot][f] = s2;
    __syncthreads();
    if (slot == 0) {
        float ts = sh[0][0][f] + sh[0][1][f] + sh[0][2][f] + sh[0][3][f];
        float t2 = sh[1][0][f] + sh[1][1][f] + sh[1][2][f] + sh[1][3][f];
        atomicAdd(g_sum + f, ts);
        atomicAdd(g_sumsq + f, t2);
    }
}

__global__ void k_bnfin(const float* __restrict__ gamma, const float* __restrict__ beta) {
    int f = threadIdx.x;
    float mu = g_sum[f] / (float)NN;
    float var = g_sumsq[f] / (float)NN - mu * mu;
    float inv = rsqrtf(var + 1e-5f);
    float sc = gamma[f] * inv;
    g_bnA[f] = sc;
    g_bnB[f] = beta[f] - mu * sc;
}

__global__ void k_bnapply() {
    int i = blockIdx.x * blockDim.x + threadIdx.x;
    if (i >= NN * HF) return;
    int node = i >> 6, f = i & 63;
    size_t idx = (size_t)node * ZF + f;
    g_z[idx] = g_z[idx] * g_bnA[f] + g_bnB[f];
}

// ---------------------------------------------------------------------------
// SpMM: dst[u] = dinv[u] * sum_{v in adj(u)} dinv[v] * src[v]  (- diag2[u]*prev[u])
// warp per node, 2 features per lane (float2).
// ---------------------------------------------------------------------------
__global__ void k_spmm(int srcInZ, int srcOff, int prevMode, int prevOff,
                       int dstOff, int writeCur) {
    int node = blockIdx.x * 4 + (threadIdx.x >> 5);
    if (node >= NN) return;
    int lane = threadIdx.x & 31;

    const float* src = srcInZ ? (g_z + srcOff) : g_curB;
    int sld = srcInZ ? ZF : HF;

    int s = g_rowptr[node];
    int e = g_rowptr[node + 1];
    float ax = 0.f, ay = 0.f;
#pragma unroll 4
    for (int j = s; j < e; j++) {
        int v = g_adj[j];
        float dv = g_dinv[v];
        float2 xv = *reinterpret_cast<const float2*>(src + (size_t)v * sld + 2 * lane);
        ax += dv * xv.x;
        ay += dv * xv.y;
    }
    float du = g_dinv[node];
    ax *= du;
    ay *= du;
    if (prevMode) {
        const float* prev = (prevMode == 1) ? (g_z + prevOff) : g_curB;
        int pld = (prevMode == 1) ? ZF : HF;
        float d2 = g_diag2[node];
        float2 p = *reinterpret_cast<const float2*>(prev + (size_t)node * pld + 2 * lane);
        ax -= d2 * p.x;
        ay -= d2 * p.y;
    }
    *reinterpret_cast<float2*>(g_z + dstOff + (size_t)node * ZF + 2 * lane) =
        make_float2(ax, ay);
    if (writeCur) {
        float2 sown = *reinterpret_cast<const float2*>(src + (size_t)node * sld + 2 * lane);
        *reinterpret_cast<float2*>(g_curB + (size_t)node * HF + 2 * lane) =
            make_float2(sown.x + ax, sown.y + ay);
    }
}

// ---------------------------------------------------------------------------
extern "C" void kernel_launch(void* const* d_in, const int* in_sizes, int n_in,
                              void* d_out, int out_size) {
    const float* x       = (const float*)d_in[0];
    const int*   ei32    = (const int*)d_in[1];
    const float* W_embed = (const float*)d_in[2];
    const float* b_embed = (const float*)d_in[3];
    const float* bn_g    = (const float*)d_in[4];
    const float* bn_b    = (const float*)d_in[5];
    const float* W1      = (const float*)d_in[6];
    const float* b1      = (const float*)d_in[7];
    const float* W2      = (const float*)d_in[8];
    const float* b2      = (const float*)d_in[9];
    float* out = (float*)d_out;

    // graph prep
    k_detect<<<1, 1>>>(ei32);
    k_init<<<256, 256>>>();
    k_deg<<<(EE + 255) / 256, 256>>>(ei32);
    k_dinv<<<(NN + 255) / 256, 256>>>();
    k_scan<<<1, 1024>>>();
    k_fill<<<(EE + 255) / 256, 256>>>(ei32);

    int mma_grid = (NN + 127) / 128;
    // embed: g_z chunk0 = relu(x @ W_embed^T + b_embed)
    k_mma<<<mma_grid, 256>>>(x, NN, INF_, INF_, W_embed, HF, INF_, b_embed,
                             nullptr, ZF, 1, /*aSel*/0, /*cSel*/1);
    // batchnorm (training stats)
    k_stats<<<256, 256>>>();
    k_bnfin<<<1, 64>>>(bn_g, bn_b);
    k_bnapply<<<(NN * HF + 255) / 256, 256>>>();

    int spmm_grid = (NN + 3) / 4;
    // hop 1: h1a = A h ; h2a = A h1a - diag2*h ; curB = h1a + h2a
    k_spmm<<<spmm_grid, 128>>>(1, 0 * HF, 0, 0, 1 * HF, 0);
    k_spmm<<<spmm_grid, 128>>>(1, 1 * HF, 1, 0 * HF, 2 * HF, 1);
    // hop 2: h1b = A curB ; h2b = A h1b - diag2*curB
    k_spmm<<<spmm_grid, 128>>>(0, 0, 0, 0, 3 * HF, 0);
    k_spmm<<<spmm_grid, 128>>>(1, 3 * HF, 2, 0, 4 * HF, 0);

    // MLP: hid = relu(z @ W1^T + b1); out = hid @ W2^T + b2
    k_mma<<<mma_grid, 256>>>(nullptr, NN, ZF, ZF, W1, HF, ZF, b1,
                             nullptr, HF, 1, /*aSel*/1, /*cSel*/2);
    k_mma<<<mma_grid, 256>>>(nullptr, NN, HF, HF, W2, CF, HF, b2,
                             out, CF, 0, /*aSel*/2, /*cSel*/0);
}

// round 5
// speedup vs baseline: 1.6854x; 1.1519x over previous
#include <cuda_runtime.h>

// ---------------------------------------------------------------------------
// H2GCN forward. tf32 tensor-core GEMMs (double-buffered), parallel scan.
// ---------------------------------------------------------------------------

#define NN   100000
#define EE   800000
#define INF_ 512
#define HF   64
#define CF   40
#define ZF   320   // 5 * HF concat width

// ---- scratch (static device globals; no allocation anywhere) ----
__device__ float g_deg[NN];
__device__ float g_dinv[NN];
__device__ float g_diag2[NN];
__device__ int   g_rowptr[NN + 1];
__device__ int   g_cursor[NN];
__device__ int   g_part[512];
__device__ int   g_adj[2 * EE];
__device__ float g_z[(size_t)NN * ZF];    // chunks: h,h1a,h2a,h1b,h2b
__device__ float g_curB[(size_t)NN * HF];
__device__ float g_hid[(size_t)NN * HF];
__device__ float g_sum[HF];
__device__ float g_sumsq[HF];
__device__ float g_bnA[HF];
__device__ float g_bnB[HF];
__device__ int   g_is64;

// ---------------------------------------------------------------------------
__device__ __forceinline__ void load_edge(const int* __restrict__ ei32, int e,
                                          int& u, int& v) {
    if (g_is64) {
        u = ei32[2 * e];
        v = ei32[2 * EE + 2 * e];
    } else {
        u = ei32[e];
        v = ei32[EE + e];
    }
}

// init + dtype probe (int64 LE values < 2^31 -> odd int32 words all zero)
__global__ void k_init(const int* __restrict__ ei32) {
    int i = blockIdx.x * blockDim.x + threadIdx.x;
    int stride = gridDim.x * blockDim.x;
    for (int j = i; j < NN; j += stride) {
        g_deg[j] = 0.f;
        g_diag2[j] = 0.f;
        g_cursor[j] = 0;
    }
    if (i < HF) { g_sum[i] = 0.f; g_sumsq[i] = 0.f; }
    if (i == 0) {
        int oddzero = 1;
#pragma unroll
        for (int q = 1; q < 16; q += 2)
            if (ei32[q] != 0) oddzero = 0;
        g_is64 = oddzero;
    }
}

__global__ void k_deg(const int* __restrict__ ei32) {
    int e = blockIdx.x * blockDim.x + threadIdx.x;
    if (e >= EE) return;
    int u, v;
    load_edge(ei32, e, u, v);
    if ((unsigned)u >= NN || (unsigned)v >= NN || u == v) return;
    atomicAdd(g_deg + u, 1.f);
    atomicAdd(g_deg + v, 1.f);
}

__global__ void k_dinv() {
    int i = blockIdx.x * blockDim.x + threadIdx.x;
    if (i < NN) {
        float d = g_deg[i];
        g_dinv[i] = (d > 0.f) ? rsqrtf(d) : 0.f;
    }
}

// ---- 3-phase exclusive scan of (int)g_deg -> g_rowptr ----
__global__ void k_scan1() {
    __shared__ int sh[256];
    int t = threadIdx.x;
    int i = blockIdx.x * 256 + t;
    sh[t] = (i < NN) ? (int)g_deg[i] : 0;
    __syncthreads();
    for (int off = 128; off > 0; off >>= 1) {
        if (t < off) sh[t] += sh[t + off];
        __syncthreads();
    }
    if (t == 0) g_part[blockIdx.x] = sh[0];
}

__global__ void k_scan2(int np) {  // 1 block, 512 threads
    __shared__ int sh[512];
    int t = threadIdx.x;
    int v = (t < np) ? g_part[t] : 0;
    sh[t] = v;
    __syncthreads();
    for (int off = 1; off < 512; off <<= 1) {
        int x = (t >= off) ? sh[t - off] : 0;
        __syncthreads();
        sh[t] += x;
        __syncthreads();
    }
    if (t < np) g_part[t] = sh[t] - v;  // exclusive
    if (t == 511) g_rowptr[NN] = sh[511];
}

__global__ void k_scan3() {
    __shared__ int sh[256];
    int t = threadIdx.x;
    int i = blockIdx.x * 256 + t;
    int v = (i < NN) ? (int)g_deg[i] : 0;
    sh[t] = v;
    __syncthreads();
    for (int off = 1; off < 256; off <<= 1) {
        int x = (t >= off) ? sh[t - off] : 0;
        __syncthreads();
        sh[t] += x;
        __syncthreads();
    }
    if (i < NN) g_rowptr[i] = g_part[blockIdx.x] + sh[t] - v;
}

__global__ void k_fill(const int* __restrict__ ei32) {
    int e = blockIdx.x * blockDim.x + threadIdx.x;
    if (e >= EE) return;
    int u, v;
    load_edge(ei32, e, u, v);
    if ((unsigned)u >= NN || (unsigned)v >= NN || u == v) return;
    float w = g_dinv[u] * g_dinv[v];
    float ww = w * w;
    atomicAdd(g_diag2 + u, ww);
    atomicAdd(g_diag2 + v, ww);
    int p = atomicAdd(g_cursor + u, 1);
    g_adj[g_rowptr[u] + p] = v;
    int q = atomicAdd(g_cursor + v, 1);
    g_adj[g_rowptr[v] + q] = u;
}

// ---------------------------------------------------------------------------
// tf32 tensor-core GEMM, double-buffered: C = act(A[MxK] @ B[NcxK]^T + bias)
// BM=128, BN=64, BK=16, 256 threads, warp tile 32x32 (mma m16n8k8).
// K % 16 == 0, Nc even, Nc <= 64.
// ---------------------------------------------------------------------------
__device__ __forceinline__ unsigned f2tf(float f) {
    unsigned r;
    asm("cvt.rna.tf32.f32 %0, %1;" : "=r"(r) : "f"(f));
    return r;
}

#define SAS 20  // smem stride: 20*g mod 32 spans 8 distinct offsets -> conflict-free

__global__ void k_mma(const float* __restrict__ Ain, int M, int K, int lda,
                      const float* __restrict__ B, int Nc, int ldb,
                      const float* __restrict__ bias,
                      float* __restrict__ Cout, int ldc, int doRelu,
                      int aSel, int cSel) {
    const float* A = (aSel == 1) ? g_z : (aSel == 2) ? g_hid : Ain;
    float* C = (cSel == 1) ? g_z : (cSel == 2) ? g_hid : Cout;

    __shared__ unsigned As[2][128 * SAS];
    __shared__ unsigned Bs[2][64 * SAS];

    int t = threadIdx.x;
    int w = t >> 5, lane = t & 31;
    int g = lane >> 2, tig = lane & 3;
    int wm = (w & 3) * 32;
    int wn = (w >> 2) * 32;
    int row0 = blockIdx.x * 128;

    float acc[2][4][4];
#pragma unroll
    for (int im = 0; im < 2; im++)
#pragma unroll
        for (int in = 0; in < 4; in++)
#pragma unroll
            for (int q = 0; q < 4; q++) acc[im][in][q] = 0.f;

    int ar = t >> 1, ac = t & 1;        // A: 2 threads/row, chunks ac and ac+2
    int br = t >> 2, bc4 = t & 3;       // B: 4 threads/row, 1 chunk each
    int gr = row0 + ar;

    float4 ra0, ra1, rb;
    const float4 z4 = make_float4(0.f, 0.f, 0.f, 0.f);

#define LOADT(k0)                                                              \
    {                                                                          \
        if (gr < M) {                                                          \
            const float* ap = A + (size_t)gr * lda + (k0);                     \
            ra0 = *reinterpret_cast<const float4*>(ap + ac * 4);               \
            ra1 = *reinterpret_cast<const float4*>(ap + (ac + 2) * 4);         \
        } else { ra0 = z4; ra1 = z4; }                                         \
        rb = (br < Nc)                                                         \
            ? *reinterpret_cast<const float4*>(B + (size_t)br * ldb + (k0) + bc4 * 4) \
            : z4;                                                              \
    }

#define STORET(bi)                                                             \
    {                                                                          \
        unsigned* d = &As[bi][ar * SAS + ac * 4];                              \
        d[0] = f2tf(ra0.x); d[1] = f2tf(ra0.y);                                \
        d[2] = f2tf(ra0.z); d[3] = f2tf(ra0.w);                                \
        d += 8;                                                                \
        d[0] = f2tf(ra1.x); d[1] = f2tf(ra1.y);                                \
        d[2] = f2tf(ra1.z); d[3] = f2tf(ra1.w);                                \
        unsigned* e2 = &Bs[bi][br * SAS + bc4 * 4];                            \
        e2[0] = f2tf(rb.x); e2[1] = f2tf(rb.y);                                \
        e2[2] = f2tf(rb.z); e2[3] = f2tf(rb.w);                                \
    }

    int iters = K >> 4;
    LOADT(0);
    STORET(0);
    __syncthreads();
    int buf = 0;

    for (int i = 0; i < iters; i++) {
        int havenext = (i + 1 < iters);
        if (havenext) LOADT((i + 1) * 16);

#pragma unroll
        for (int ks = 0; ks < 2; ks++) {
            int kb = ks * 8;
            unsigned a[2][4];
#pragma unroll
            for (int im = 0; im < 2; im++) {
                int r = wm + im * 16;
                a[im][0] = As[buf][(r + g) * SAS + kb + tig];
                a[im][1] = As[buf][(r + g + 8) * SAS + kb + tig];
                a[im][2] = As[buf][(r + g) * SAS + kb + tig + 4];
                a[im][3] = As[buf][(r + g + 8) * SAS + kb + tig + 4];
            }
            unsigned b[4][2];
#pragma unroll
            for (int in = 0; in < 4; in++) {
                int c = wn + in * 8;
                b[in][0] = Bs[buf][(c + g) * SAS + kb + tig];
                b[in][1] = Bs[buf][(c + g) * SAS + kb + tig + 4];
            }
#pragma unroll
            for (int im = 0; im < 2; im++)
#pragma unroll
                for (int in = 0; in < 4; in++) {
                    asm volatile(
                        "mma.sync.aligned.m16n8k8.row.col.f32.tf32.tf32.f32 "
                        "{%0,%1,%2,%3}, {%4,%5,%6,%7}, {%8,%9}, {%0,%1,%2,%3};"
                        : "+f"(acc[im][in][0]), "+f"(acc[im][in][1]),
                          "+f"(acc[im][in][2]), "+f"(acc[im][in][3])
                        : "r"(a[im][0]), "r"(a[im][1]), "r"(a[im][2]), "r"(a[im][3]),
                          "r"(b[in][0]), "r"(b[in][1]));
                }
        }

        if (havenext) {
            STORET(buf ^ 1);
            __syncthreads();
            buf ^= 1;
        }
    }

    // epilogue
#pragma unroll
    for (int im = 0; im < 2; im++) {
#pragma unroll
        for (int in = 0; in < 4; in++) {
            int Cc = wn + in * 8 + 2 * tig;
            if (Cc >= Nc) continue;
            float bx = bias[Cc], by = bias[Cc + 1];
            int R0 = row0 + wm + im * 16 + g;
            float v0 = acc[im][in][0] + bx;
            float v1 = acc[im][in][1] + by;
            float v2 = acc[im][in][2] + bx;
            float v3 = acc[im][in][3] + by;
            if (doRelu) {
                v0 = fmaxf(v0, 0.f); v1 = fmaxf(v1, 0.f);
                v2 = fmaxf(v2, 0.f); v3 = fmaxf(v3, 0.f);
            }
            if (R0 < M)
                *reinterpret_cast<float2*>(C + (size_t)R0 * ldc + Cc) = make_float2(v0, v1);
            if (R0 + 8 < M)
                *reinterpret_cast<float2*>(C + (size_t)(R0 + 8) * ldc + Cc) = make_float2(v2, v3);
        }
    }
#undef LOADT
#undef STORET
}

// ---------------------------------------------------------------------------
__global__ void k_stats() {
    int f = threadIdx.x & 63;
    int slot = threadIdx.x >> 6;
    float s = 0.f, s2 = 0.f;
    for (int i = blockIdx.x * 4 + slot; i < NN; i += gridDim.x * 4) {
        float v = g_z[(size_t)i * ZF + f];
        s += v;
        s2 += v * v;
    }
    __shared__ float sh[2][4][64];
    sh[0][slot][f] = s;
    sh[1][slot][f] = s2;
    __syncthreads();
    if (slot == 0) {
        float ts = sh[0][0][f] + sh[0][1][f] + sh[0][2][f] + sh[0][3][f];
        float t2 = sh[1][0][f] + sh[1][1][f] + sh[1][2][f] + sh[1][3][f];
        atomicAdd(g_sum + f, ts);
        atomicAdd(g_sumsq + f, t2);
    }
}

__global__ void k_bnfin(const float* __restrict__ gamma, const float* __restrict__ beta) {
    int f = threadIdx.x;
    float mu = g_sum[f] / (float)NN;
    float var = g_sumsq[f] / (float)NN - mu * mu;
    float inv = rsqrtf(var + 1e-5f);
    float sc = gamma[f] * inv;
    g_bnA[f] = sc;
    g_bnB[f] = beta[f] - mu * sc;
}

__global__ void k_bnapply() {
    int i = blockIdx.x * blockDim.x + threadIdx.x;
    if (i >= NN * HF) return;
    int node = i >> 6, f = i & 63;
    size_t idx = (size_t)node * ZF + f;
    g_z[idx] = g_z[idx] * g_bnA[f] + g_bnB[f];
}

// ---------------------------------------------------------------------------
// SpMM: dst[u] = dinv[u] * sum_{v in adj(u)} dinv[v] * src[v]  (- diag2[u]*prev[u])
// warp per node, 2 features per lane (float2).
// ---------------------------------------------------------------------------
__global__ void k_spmm(int srcInZ, int srcOff, int prevMode, int prevOff,
                       int dstOff, int writeCur) {
    int node = blockIdx.x * 4 + (threadIdx.x >> 5);
    if (node >= NN) return;
    int lane = threadIdx.x & 31;

    const float* src = srcInZ ? (g_z + srcOff) : g_curB;
    int sld = srcInZ ? ZF : HF;

    int s = g_rowptr[node];
    int e = g_rowptr[node + 1];
    float ax = 0.f, ay = 0.f;
#pragma unroll 4
    for (int j = s; j < e; j++) {
        int v = g_adj[j];
        float dv = g_dinv[v];
        float2 xv = *reinterpret_cast<const float2*>(src + (size_t)v * sld + 2 * lane);
        ax += dv * xv.x;
        ay += dv * xv.y;
    }
    float du = g_dinv[node];
    ax *= du;
    ay *= du;
    if (prevMode) {
        const float* prev = (prevMode == 1) ? (g_z + prevOff) : g_curB;
        int pld = (prevMode == 1) ? ZF : HF;
        float d2 = g_diag2[node];
        float2 p = *reinterpret_cast<const float2*>(prev + (size_t)node * pld + 2 * lane);
        ax -= d2 * p.x;
        ay -= d2 * p.y;
    }
    *reinterpret_cast<float2*>(g_z + dstOff + (size_t)node * ZF + 2 * lane) =
        make_float2(ax, ay);
    if (writeCur) {
        float2 sown = *reinterpret_cast<const float2*>(src + (size_t)node * sld + 2 * lane);
        *reinterpret_cast<float2*>(g_curB + (size_t)node * HF + 2 * lane) =
            make_float2(sown.x + ax, sown.y + ay);
    }
}

// ---------------------------------------------------------------------------
extern "C" void kernel_launch(void* const* d_in, const int* in_sizes, int n_in,
                              void* d_out, int out_size) {
    const float* x       = (const float*)d_in[0];
    const int*   ei32    = (const int*)d_in[1];
    const float* W_embed = (const float*)d_in[2];
    const float* b_embed = (const float*)d_in[3];
    const float* bn_g    = (const float*)d_in[4];
    const float* bn_b    = (const float*)d_in[5];
    const float* W1      = (const float*)d_in[6];
    const float* b1      = (const float*)d_in[7];
    const float* W2      = (const float*)d_in[8];
    const float* b2      = (const float*)d_in[9];
    float* out = (float*)d_out;

    const int NPART = (NN + 255) / 256;  // 391

    // graph prep
    k_init<<<256, 256>>>(ei32);
    k_deg<<<(EE + 255) / 256, 256>>>(ei32);
    k_dinv<<<(NN + 255) / 256, 256>>>();
    k_scan1<<<NPART, 256>>>();
    k_scan2<<<1, 512>>>(NPART);
    k_scan3<<<NPART, 256>>>();
    k_fill<<<(EE + 255) / 256, 256>>>(ei32);

    int mma_grid = (NN + 127) / 128;
    // embed: g_z chunk0 = relu(x @ W_embed^T + b_embed)
    k_mma<<<mma_grid, 256>>>(x, NN, INF_, INF_, W_embed, HF, INF_, b_embed,
                             nullptr, ZF, 1, /*aSel*/0, /*cSel*/1);
    // batchnorm (training stats)
    k_stats<<<256, 256>>>();
    k_bnfin<<<1, 64>>>(bn_g, bn_b);
    k_bnapply<<<(NN * HF + 255) / 256, 256>>>();

    int spmm_grid = (NN + 3) / 4;
    // hop 1
    k_spmm<<<spmm_grid, 128>>>(1, 0 * HF, 0, 0, 1 * HF, 0);
    k_spmm<<<spmm_grid, 128>>>(1, 1 * HF, 1, 0 * HF, 2 * HF, 1);
    // hop 2
    k_spmm<<<spmm_grid, 128>>>(0, 0, 0, 0, 3 * HF, 0);
    k_spmm<<<spmm_grid, 128>>>(1, 3 * HF, 2, 0, 4 * HF, 0);

    // MLP
    k_mma<<<mma_grid, 256>>>(nullptr, NN, ZF, ZF, W1, HF, ZF, b1,
                             nullptr, HF, 1, /*aSel*/1, /*cSel*/2);
    k_mma<<<mma_grid, 256>>>(nullptr, NN, HF, HF, W2, CF, HF, b2,
                             out, CF, 0, /*aSel*/2, /*cSel*/0);
}

// round 6
// speedup vs baseline: 1.8893x; 1.1210x over previous
#include <cuda_runtime.h>

// ---------------------------------------------------------------------------
// H2GCN forward. tf32 tensor-core GEMMs (double-buffered), parallel scan,
// half-warp-per-node SpMM (float4 lanes).
// ---------------------------------------------------------------------------

#define NN   100000
#define EE   800000
#define INF_ 512
#define HF   64
#define CF   40
#define ZF   320   // 5 * HF concat width

// ---- scratch (static device globals; no allocation anywhere) ----
__device__ float g_deg[NN];
__device__ float g_dinv[NN];
__device__ float g_diag2[NN];
__device__ int   g_rowptr[NN + 1];
__device__ int   g_cursor[NN];
__device__ int   g_part[512];
__device__ int   g_adj[2 * EE];
__device__ float g_z[(size_t)NN * ZF];    // chunks: h,h1a,h2a,h1b,h2b
__device__ float g_curB[(size_t)NN * HF];
__device__ float g_hid[(size_t)NN * HF];
__device__ float g_sum[HF];
__device__ float g_sumsq[HF];
__device__ float g_bnA[HF];
__device__ float g_bnB[HF];
__device__ int   g_is64;

// ---------------------------------------------------------------------------
__device__ __forceinline__ void load_edge(const int* __restrict__ ei32, int e,
                                          int& u, int& v) {
    if (g_is64) {
        u = ei32[2 * e];
        v = ei32[2 * EE + 2 * e];
    } else {
        u = ei32[e];
        v = ei32[EE + e];
    }
}

// init + dtype probe (int64 LE values < 2^31 -> odd int32 words all zero)
__global__ void k_init(const int* __restrict__ ei32) {
    int i = blockIdx.x * blockDim.x + threadIdx.x;
    int stride = gridDim.x * blockDim.x;
    for (int j = i; j < NN; j += stride) {
        g_deg[j] = 0.f;
        g_diag2[j] = 0.f;
        g_cursor[j] = 0;
    }
    if (i < HF) { g_sum[i] = 0.f; g_sumsq[i] = 0.f; }
    if (i == 0) {
        int oddzero = 1;
#pragma unroll
        for (int q = 1; q < 16; q += 2)
            if (ei32[q] != 0) oddzero = 0;
        g_is64 = oddzero;
    }
}

__global__ void k_deg(const int* __restrict__ ei32) {
    int e = blockIdx.x * blockDim.x + threadIdx.x;
    if (e >= EE) return;
    int u, v;
    load_edge(ei32, e, u, v);
    if ((unsigned)u >= NN || (unsigned)v >= NN || u == v) return;
    atomicAdd(g_deg + u, 1.f);
    atomicAdd(g_deg + v, 1.f);
}

// ---- 3-phase exclusive scan of (int)g_deg -> g_rowptr; also emits dinv ----
__global__ void k_scan1() {
    __shared__ int sh[256];
    int t = threadIdx.x;
    int i = blockIdx.x * 256 + t;
    float d = (i < NN) ? g_deg[i] : 0.f;
    if (i < NN) g_dinv[i] = (d > 0.f) ? rsqrtf(d) : 0.f;
    sh[t] = (int)d;
    __syncthreads();
    for (int off = 128; off > 0; off >>= 1) {
        if (t < off) sh[t] += sh[t + off];
        __syncthreads();
    }
    if (t == 0) g_part[blockIdx.x] = sh[0];
}

__global__ void k_scan2(int np) {  // 1 block, 512 threads
    __shared__ int sh[512];
    int t = threadIdx.x;
    int v = (t < np) ? g_part[t] : 0;
    sh[t] = v;
    __syncthreads();
    for (int off = 1; off < 512; off <<= 1) {
        int x = (t >= off) ? sh[t - off] : 0;
        __syncthreads();
        sh[t] += x;
        __syncthreads();
    }
    if (t < np) g_part[t] = sh[t] - v;  // exclusive
    if (t == 511) g_rowptr[NN] = sh[511];
}

__global__ void k_scan3() {
    __shared__ int sh[256];
    int t = threadIdx.x;
    int i = blockIdx.x * 256 + t;
    int v = (i < NN) ? (int)g_deg[i] : 0;
    sh[t] = v;
    __syncthreads();
    for (int off = 1; off < 256; off <<= 1) {
        int x = (t >= off) ? sh[t - off] : 0;
        __syncthreads();
        sh[t] += x;
        __syncthreads();
    }
    if (i < NN) g_rowptr[i] = g_part[blockIdx.x] + sh[t] - v;
}

__global__ void k_fill(const int* __restrict__ ei32) {
    int e = blockIdx.x * blockDim.x + threadIdx.x;
    if (e >= EE) return;
    int u, v;
    load_edge(ei32, e, u, v);
    if ((unsigned)u >= NN || (unsigned)v >= NN || u == v) return;
    float w = g_dinv[u] * g_dinv[v];
    float ww = w * w;
    atomicAdd(g_diag2 + u, ww);
    atomicAdd(g_diag2 + v, ww);
    int p = atomicAdd(g_cursor + u, 1);
    g_adj[g_rowptr[u] + p] = v;
    int q = atomicAdd(g_cursor + v, 1);
    g_adj[g_rowptr[v] + q] = u;
}

// ---------------------------------------------------------------------------
// tf32 tensor-core GEMM, double-buffered: C = act(A[MxK] @ B[NcxK]^T + bias)
// BM=128, BN=64, BK=16, 256 threads, warp tile 32x32 (mma m16n8k8).
// ---------------------------------------------------------------------------
__device__ __forceinline__ unsigned f2tf(float f) {
    unsigned r;
    asm("cvt.rna.tf32.f32 %0, %1;" : "=r"(r) : "f"(f));
    return r;
}

#define SAS 20

__global__ void k_mma(const float* __restrict__ Ain, int M, int K, int lda,
                      const float* __restrict__ B, int Nc, int ldb,
                      const float* __restrict__ bias,
                      float* __restrict__ Cout, int ldc, int doRelu,
                      int aSel, int cSel) {
    const float* A = (aSel == 1) ? g_z : (aSel == 2) ? g_hid : Ain;
    float* C = (cSel == 1) ? g_z : (cSel == 2) ? g_hid : Cout;

    __shared__ unsigned As[2][128 * SAS];
    __shared__ unsigned Bs[2][64 * SAS];

    int t = threadIdx.x;
    int w = t >> 5, lane = t & 31;
    int g = lane >> 2, tig = lane & 3;
    int wm = (w & 3) * 32;
    int wn = (w >> 2) * 32;
    int row0 = blockIdx.x * 128;

    float acc[2][4][4];
#pragma unroll
    for (int im = 0; im < 2; im++)
#pragma unroll
        for (int in = 0; in < 4; in++)
#pragma unroll
            for (int q = 0; q < 4; q++) acc[im][in][q] = 0.f;

    int ar = t >> 1, ac = t & 1;
    int br = t >> 2, bc4 = t & 3;
    int gr = row0 + ar;

    float4 ra0, ra1, rb;
    const float4 z4 = make_float4(0.f, 0.f, 0.f, 0.f);

#define LOADT(k0)                                                              \
    {                                                                          \
        if (gr < M) {                                                          \
            const float* ap = A + (size_t)gr * lda + (k0);                     \
            ra0 = *reinterpret_cast<const float4*>(ap + ac * 4);               \
            ra1 = *reinterpret_cast<const float4*>(ap + (ac + 2) * 4);         \
        } else { ra0 = z4; ra1 = z4; }                                         \
        rb = (br < Nc)                                                         \
            ? *reinterpret_cast<const float4*>(B + (size_t)br * ldb + (k0) + bc4 * 4) \
            : z4;                                                              \
    }

#define STORET(bi)                                                             \
    {                                                                          \
        unsigned* d = &As[bi][ar * SAS + ac * 4];                              \
        d[0] = f2tf(ra0.x); d[1] = f2tf(ra0.y);                                \
        d[2] = f2tf(ra0.z); d[3] = f2tf(ra0.w);                                \
        d += 8;                                                                \
        d[0] = f2tf(ra1.x); d[1] = f2tf(ra1.y);                                \
        d[2] = f2tf(ra1.z); d[3] = f2tf(ra1.w);                                \
        unsigned* e2 = &Bs[bi][br * SAS + bc4 * 4];                            \
        e2[0] = f2tf(rb.x); e2[1] = f2tf(rb.y);                                \
        e2[2] = f2tf(rb.z); e2[3] = f2tf(rb.w);                                \
    }

    int iters = K >> 4;
    LOADT(0);
    STORET(0);
    __syncthreads();
    int buf = 0;

    for (int i = 0; i < iters; i++) {
        int havenext = (i + 1 < iters);
        if (havenext) LOADT((i + 1) * 16);

#pragma unroll
        for (int ks = 0; ks < 2; ks++) {
            int kb = ks * 8;
            unsigned a[2][4];
#pragma unroll
            for (int im = 0; im < 2; im++) {
                int r = wm + im * 16;
                a[im][0] = As[buf][(r + g) * SAS + kb + tig];
                a[im][1] = As[buf][(r + g + 8) * SAS + kb + tig];
                a[im][2] = As[buf][(r + g) * SAS + kb + tig + 4];
                a[im][3] = As[buf][(r + g + 8) * SAS + kb + tig + 4];
            }
            unsigned b[4][2];
#pragma unroll
            for (int in = 0; in < 4; in++) {
                int c = wn + in * 8;
                b[in][0] = Bs[buf][(c + g) * SAS + kb + tig];
                b[in][1] = Bs[buf][(c + g) * SAS + kb + tig + 4];
            }
#pragma unroll
            for (int im = 0; im < 2; im++)
#pragma unroll
                for (int in = 0; in < 4; in++) {
                    asm volatile(
                        "mma.sync.aligned.m16n8k8.row.col.f32.tf32.tf32.f32 "
                        "{%0,%1,%2,%3}, {%4,%5,%6,%7}, {%8,%9}, {%0,%1,%2,%3};"
                        : "+f"(acc[im][in][0]), "+f"(acc[im][in][1]),
                          "+f"(acc[im][in][2]), "+f"(acc[im][in][3])
                        : "r"(a[im][0]), "r"(a[im][1]), "r"(a[im][2]), "r"(a[im][3]),
                          "r"(b[in][0]), "r"(b[in][1]));
                }
        }

        if (havenext) {
            STORET(buf ^ 1);
            __syncthreads();
            buf ^= 1;
        }
    }

    // epilogue
#pragma unroll
    for (int im = 0; im < 2; im++) {
#pragma unroll
        for (int in = 0; in < 4; in++) {
            int Cc = wn + in * 8 + 2 * tig;
            if (Cc >= Nc) continue;
            float bx = bias[Cc], by = bias[Cc + 1];
            int R0 = row0 + wm + im * 16 + g;
            float v0 = acc[im][in][0] + bx;
            float v1 = acc[im][in][1] + by;
            float v2 = acc[im][in][2] + bx;
            float v3 = acc[im][in][3] + by;
            if (doRelu) {
                v0 = fmaxf(v0, 0.f); v1 = fmaxf(v1, 0.f);
                v2 = fmaxf(v2, 0.f); v3 = fmaxf(v3, 0.f);
            }
            if (R0 < M)
                *reinterpret_cast<float2*>(C + (size_t)R0 * ldc + Cc) = make_float2(v0, v1);
            if (R0 + 8 < M)
                *reinterpret_cast<float2*>(C + (size_t)(R0 + 8) * ldc + Cc) = make_float2(v2, v3);
        }
    }
#undef LOADT
#undef STORET
}

// ---------------------------------------------------------------------------
__global__ void k_stats() {
    int f = threadIdx.x & 63;
    int slot = threadIdx.x >> 6;
    float s = 0.f, s2 = 0.f;
    for (int i = blockIdx.x * 4 + slot; i < NN; i += gridDim.x * 4) {
        float v = g_z[(size_t)i * ZF + f];
        s += v;
        s2 += v * v;
    }
    __shared__ float sh[2][4][64];
    sh[0][slot][f] = s;
    sh[1][slot][f] = s2;
    __syncthreads();
    if (slot == 0) {
        float ts = sh[0][0][f] + sh[0][1][f] + sh[0][2][f] + sh[0][3][f];
        float t2 = sh[1][0][f] + sh[1][1][f] + sh[1][2][f] + sh[1][3][f];
        atomicAdd(g_sum + f, ts);
        atomicAdd(g_sumsq + f, t2);
    }
}

__global__ void k_bnfin(const float* __restrict__ gamma, const float* __restrict__ beta) {
    int f = threadIdx.x;
    float mu = g_sum[f] / (float)NN;
    float var = g_sumsq[f] / (float)NN - mu * mu;
    float inv = rsqrtf(var + 1e-5f);
    float sc = gamma[f] * inv;
    g_bnA[f] = sc;
    g_bnB[f] = beta[f] - mu * sc;
}

__global__ void k_bnapply() {
    int i = blockIdx.x * blockDim.x + threadIdx.x;
    if (i >= NN * HF) return;
    int node = i >> 6, f = i & 63;
    size_t idx = (size_t)node * ZF + f;
    g_z[idx] = g_z[idx] * g_bnA[f] + g_bnB[f];
}

// ---------------------------------------------------------------------------
// SpMM: dst[u] = dinv[u] * sum_{v in adj(u)} dinv[v] * src[v]  (- diag2[u]*prev[u])
// HALF-WARP per node: 16 lanes x float4 = 64 features.
// ---------------------------------------------------------------------------
__global__ void k_spmm(int srcInZ, int srcOff, int prevMode, int prevOff,
                       int dstOff, int writeCur) {
    int node = blockIdx.x * 16 + (threadIdx.x >> 4);
    if (node >= NN) return;
    int l4 = (threadIdx.x & 15) * 4;

    const float* src = srcInZ ? (g_z + srcOff) : g_curB;
    int sld = srcInZ ? ZF : HF;

    int s = g_rowptr[node];
    int e = g_rowptr[node + 1];
    float ax = 0.f, ay = 0.f, az = 0.f, aw = 0.f;
#pragma unroll 4
    for (int j = s; j < e; j++) {
        int v = g_adj[j];
        float dv = g_dinv[v];
        float4 xv = *reinterpret_cast<const float4*>(src + (size_t)v * sld + l4);
        ax += dv * xv.x;
        ay += dv * xv.y;
        az += dv * xv.z;
        aw += dv * xv.w;
    }
    float du = g_dinv[node];
    ax *= du; ay *= du; az *= du; aw *= du;
    if (prevMode) {
        const float* prev = (prevMode == 1) ? (g_z + prevOff) : g_curB;
        int pld = (prevMode == 1) ? ZF : HF;
        float d2 = g_diag2[node];
        float4 p = *reinterpret_cast<const float4*>(prev + (size_t)node * pld + l4);
        ax -= d2 * p.x;
        ay -= d2 * p.y;
        az -= d2 * p.z;
        aw -= d2 * p.w;
    }
    *reinterpret_cast<float4*>(g_z + dstOff + (size_t)node * ZF + l4) =
        make_float4(ax, ay, az, aw);
    if (writeCur) {
        float4 sown = *reinterpret_cast<const float4*>(src + (size_t)node * sld + l4);
        *reinterpret_cast<float4*>(g_curB + (size_t)node * HF + l4) =
            make_float4(sown.x + ax, sown.y + ay, sown.z + az, sown.w + aw);
    }
}

// ---------------------------------------------------------------------------
extern "C" void kernel_launch(void* const* d_in, const int* in_sizes, int n_in,
                              void* d_out, int out_size) {
    const float* x       = (const float*)d_in[0];
    const int*   ei32    = (const int*)d_in[1];
    const float* W_embed = (const float*)d_in[2];
    const float* b_embed = (const float*)d_in[3];
    const float* bn_g    = (const float*)d_in[4];
    const float* bn_b    = (const float*)d_in[5];
    const float* W1      = (const float*)d_in[6];
    const float* b1      = (const float*)d_in[7];
    const float* W2      = (const float*)d_in[8];
    const float* b2      = (const float*)d_in[9];
    float* out = (float*)d_out;

    const int NPART = (NN + 255) / 256;  // 391
    int mma_grid = (NN + 127) / 128;

    // launches 0..4: prep (dinv folded into scan1)
    k_init<<<256, 256>>>(ei32);
    k_deg<<<(EE + 255) / 256, 256>>>(ei32);
    k_scan1<<<NPART, 256>>>();
    k_scan2<<<1, 512>>>(NPART);
    k_scan3<<<NPART, 256>>>();

    // launch 5: embed GEMM (independent of graph prep -> profiled by ncu -s 5)
    k_mma<<<mma_grid, 256>>>(x, NN, INF_, INF_, W_embed, HF, INF_, b_embed,
                             nullptr, ZF, 1, /*aSel*/0, /*cSel*/1);

    // launch 6: adjacency fill (needs dinv + rowptr)
    k_fill<<<(EE + 255) / 256, 256>>>(ei32);

    // batchnorm (training stats)
    k_stats<<<256, 256>>>();
    k_bnfin<<<1, 64>>>(bn_g, bn_b);
    k_bnapply<<<(NN * HF + 255) / 256, 256>>>();

    int spmm_grid = (NN + 15) / 16;
    // hop 1
    k_spmm<<<spmm_grid, 256>>>(1, 0 * HF, 0, 0, 1 * HF, 0);
    k_spmm<<<spmm_grid, 256>>>(1, 1 * HF, 1, 0 * HF, 2 * HF, 1);
    // hop 2
    k_spmm<<<spmm_grid, 256>>>(0, 0, 0, 0, 3 * HF, 0);
    k_spmm<<<spmm_grid, 256>>>(1, 3 * HF, 2, 0, 4 * HF, 0);

    // MLP
    k_mma<<<mma_grid, 256>>>(nullptr, NN, ZF, ZF, W1, HF, ZF, b1,
                             nullptr, HF, 1, /*aSel*/1, /*cSel*/2);
    k_mma<<<mma_grid, 256>>>(nullptr, NN, HF, HF, W2, CF, HF, b2,
                             out, CF, 0, /*aSel*/2, /*cSel*/0);
}

// round 7
// speedup vs baseline: 1.9659x; 1.0405x over previous
#include <cuda_runtime.h>

// ---------------------------------------------------------------------------
// H2GCN forward. tf32 tensor-core GEMMs (double-buffered, ldmatrix fragment
// loads), parallel scan, half-warp-per-node SpMM (float4 lanes).
// ---------------------------------------------------------------------------

#define NN   100000
#define EE   800000
#define INF_ 512
#define HF   64
#define CF   40
#define ZF   320   // 5 * HF concat width

// ---- scratch (static device globals; no allocation anywhere) ----
__device__ float g_deg[NN];
__device__ float g_dinv[NN];
__device__ float g_diag2[NN];
__device__ int   g_rowptr[NN + 1];
__device__ int   g_cursor[NN];
__device__ int   g_part[512];
__device__ int   g_adj[2 * EE];
__device__ float g_z[(size_t)NN * ZF];    // chunks: h,h1a,h2a,h1b,h2b
__device__ float g_curB[(size_t)NN * HF];
__device__ float g_hid[(size_t)NN * HF];
__device__ float g_sum[HF];
__device__ float g_sumsq[HF];
__device__ int   g_is64;

// ---------------------------------------------------------------------------
__device__ __forceinline__ void load_edge(const int* __restrict__ ei32, int e,
                                          int& u, int& v) {
    if (g_is64) {
        u = ei32[2 * e];
        v = ei32[2 * EE + 2 * e];
    } else {
        u = ei32[e];
        v = ei32[EE + e];
    }
}

// init + dtype probe (int64 LE values < 2^31 -> odd int32 words all zero)
__global__ void k_init(const int* __restrict__ ei32) {
    int i = blockIdx.x * blockDim.x + threadIdx.x;
    int stride = gridDim.x * blockDim.x;
    for (int j = i; j < NN; j += stride) {
        g_deg[j] = 0.f;
        g_diag2[j] = 0.f;
        g_cursor[j] = 0;
    }
    if (i < HF) { g_sum[i] = 0.f; g_sumsq[i] = 0.f; }
    if (i == 0) {
        int oddzero = 1;
#pragma unroll
        for (int q = 1; q < 16; q += 2)
            if (ei32[q] != 0) oddzero = 0;
        g_is64 = oddzero;
    }
}

__global__ void k_deg(const int* __restrict__ ei32) {
    int e = blockIdx.x * blockDim.x + threadIdx.x;
    if (e >= EE) return;
    int u, v;
    load_edge(ei32, e, u, v);
    if ((unsigned)u >= NN || (unsigned)v >= NN || u == v) return;
    atomicAdd(g_deg + u, 1.f);
    atomicAdd(g_deg + v, 1.f);
}

// ---- 3-phase exclusive scan of (int)g_deg -> g_rowptr; also emits dinv ----
__global__ void k_scan1() {
    __shared__ int sh[256];
    int t = threadIdx.x;
    int i = blockIdx.x * 256 + t;
    float d = (i < NN) ? g_deg[i] : 0.f;
    if (i < NN) g_dinv[i] = (d > 0.f) ? rsqrtf(d) : 0.f;
    sh[t] = (int)d;
    __syncthreads();
    for (int off = 128; off > 0; off >>= 1) {
        if (t < off) sh[t] += sh[t + off];
        __syncthreads();
    }
    if (t == 0) g_part[blockIdx.x] = sh[0];
}

__global__ void k_scan2(int np) {  // 1 block, 512 threads
    __shared__ int sh[512];
    int t = threadIdx.x;
    int v = (t < np) ? g_part[t] : 0;
    sh[t] = v;
    __syncthreads();
    for (int off = 1; off < 512; off <<= 1) {
        int x = (t >= off) ? sh[t - off] : 0;
        __syncthreads();
        sh[t] += x;
        __syncthreads();
    }
    if (t < np) g_part[t] = sh[t] - v;  // exclusive
    if (t == 511) g_rowptr[NN] = sh[511];
}

__global__ void k_scan3() {
    __shared__ int sh[256];
    int t = threadIdx.x;
    int i = blockIdx.x * 256 + t;
    int v = (i < NN) ? (int)g_deg[i] : 0;
    sh[t] = v;
    __syncthreads();
    for (int off = 1; off < 256; off <<= 1) {
        int x = (t >= off) ? sh[t - off] : 0;
        __syncthreads();
        sh[t] += x;
        __syncthreads();
    }
    if (i < NN) g_rowptr[i] = g_part[blockIdx.x] + sh[t] - v;
}

__global__ void k_fill(const int* __restrict__ ei32) {
    int e = blockIdx.x * blockDim.x + threadIdx.x;
    if (e >= EE) return;
    int u, v;
    load_edge(ei32, e, u, v);
    if ((unsigned)u >= NN || (unsigned)v >= NN || u == v) return;
    float w = g_dinv[u] * g_dinv[v];
    float ww = w * w;
    atomicAdd(g_diag2 + u, ww);
    atomicAdd(g_diag2 + v, ww);
    int p = atomicAdd(g_cursor + u, 1);
    g_adj[g_rowptr[u] + p] = v;
    int q = atomicAdd(g_cursor + v, 1);
    g_adj[g_rowptr[v] + q] = u;
}

// ---------------------------------------------------------------------------
// tf32 tensor-core GEMM, double-buffered + ldmatrix:
// C = act(A[MxK] @ B[NcxK]^T + bias). BM=128, BN=64, BK=16, 256 threads.
// ---------------------------------------------------------------------------
__device__ __forceinline__ unsigned f2tf(float f) {
    unsigned r;
    asm("cvt.rna.tf32.f32 %0, %1;" : "=r"(r) : "f"(f));
    return r;
}

#define SAS 20  // row stride (words): 20r mod 32 distinct over r=0..7 -> conflict-free

__device__ __forceinline__ void ldsm4(unsigned& r0, unsigned& r1,
                                      unsigned& r2, unsigned& r3, unsigned addr) {
    asm volatile("ldmatrix.sync.aligned.m8n8.x4.shared.b16 {%0,%1,%2,%3}, [%4];"
                 : "=r"(r0), "=r"(r1), "=r"(r2), "=r"(r3) : "r"(addr));
}

__global__ void k_mma(const float* __restrict__ Ain, int M, int K, int lda,
                      const float* __restrict__ B, int Nc, int ldb,
                      const float* __restrict__ bias,
                      float* __restrict__ Cout, int ldc, int doRelu,
                      int aSel, int cSel) {
    const float* A = (aSel == 1) ? g_z : (aSel == 2) ? g_hid : Ain;
    float* C = (cSel == 1) ? g_z : (cSel == 2) ? g_hid : Cout;

    __shared__ unsigned As[2][128 * SAS];
    __shared__ unsigned Bs[2][64 * SAS];

    int t = threadIdx.x;
    int w = t >> 5, lane = t & 31;
    int g = lane >> 2, tig = lane & 3;
    int wm = (w & 3) * 32;
    int wn = (w >> 2) * 32;
    int row0 = blockIdx.x * 128;

    float acc[2][4][4];
#pragma unroll
    for (int im = 0; im < 2; im++)
#pragma unroll
        for (int in = 0; in < 4; in++)
#pragma unroll
            for (int q = 0; q < 4; q++) acc[im][in][q] = 0.f;

    int ar = t >> 1, ac = t & 1;
    int br = t >> 2, bc4 = t & 3;
    int gr = row0 + ar;

    // ldmatrix per-lane source rows: lane provides addr for tile (lane>>3), row (lane&7)
    int lrow = lane & 7, lt = lane >> 3;
    // A tiles: t0=(r+0,c+0) t1=(r+8,c+0) t2=(r+0,c+4) t3=(r+8,c+4)
    int aoffw = (wm + (lt & 1) * 8 + lrow) * SAS + (lt >> 1) * 4;
    // B tiles: t0=(n+0,c+0) t1=(n+0,c+4) t2=(n+8,c+0) t3=(n+8,c+4)
    int boffw = (wn + (lt >> 1) * 8 + lrow) * SAS + (lt & 1) * 4;
    unsigned sa_A = (unsigned)__cvta_generic_to_shared(&As[0][0]);
    unsigned sa_B = (unsigned)__cvta_generic_to_shared(&Bs[0][0]);

    float4 ra0, ra1, rb;
    const float4 z4 = make_float4(0.f, 0.f, 0.f, 0.f);

#define LOADT(k0)                                                              \
    {                                                                          \
        if (gr < M) {                                                          \
            const float* ap = A + (size_t)gr * lda + (k0);                     \
            ra0 = *reinterpret_cast<const float4*>(ap + ac * 4);               \
            ra1 = *reinterpret_cast<const float4*>(ap + (ac + 2) * 4);         \
        } else { ra0 = z4; ra1 = z4; }                                         \
        rb = (br < Nc)                                                         \
            ? *reinterpret_cast<const float4*>(B + (size_t)br * ldb + (k0) + bc4 * 4) \
            : z4;                                                              \
    }

#define STORET(bi)                                                             \
    {                                                                          \
        unsigned* d = &As[bi][ar * SAS + ac * 4];                              \
        d[0] = f2tf(ra0.x); d[1] = f2tf(ra0.y);                                \
        d[2] = f2tf(ra0.z); d[3] = f2tf(ra0.w);                                \
        d += 8;                                                                \
        d[0] = f2tf(ra1.x); d[1] = f2tf(ra1.y);                                \
        d[2] = f2tf(ra1.z); d[3] = f2tf(ra1.w);                                \
        unsigned* e2 = &Bs[bi][br * SAS + bc4 * 4];                            \
        e2[0] = f2tf(rb.x); e2[1] = f2tf(rb.y);                                \
        e2[2] = f2tf(rb.z); e2[3] = f2tf(rb.w);                                \
    }

    int iters = K >> 4;
    LOADT(0);
    STORET(0);
    __syncthreads();
    int buf = 0;

    for (int i = 0; i < iters; i++) {
        int havenext = (i + 1 < iters);
        if (havenext) LOADT((i + 1) * 16);

        unsigned aB = sa_A + (unsigned)(buf * (128 * SAS * 4) + aoffw * 4);
        unsigned bB = sa_B + (unsigned)(buf * (64 * SAS * 4) + boffw * 4);

#pragma unroll
        for (int ks = 0; ks < 2; ks++) {
            unsigned kbb = ks * 32;  // kb*4 bytes, kb = ks*8 words
            unsigned a[2][4];
            ldsm4(a[0][0], a[0][1], a[0][2], a[0][3], aB + kbb);
            ldsm4(a[1][0], a[1][1], a[1][2], a[1][3], aB + kbb + 16 * SAS * 4);
            unsigned b[4][2];
            ldsm4(b[0][0], b[0][1], b[1][0], b[1][1], bB + kbb);
            ldsm4(b[2][0], b[2][1], b[3][0], b[3][1], bB + kbb + 16 * SAS * 4);
#pragma unroll
            for (int im = 0; im < 2; im++)
#pragma unroll
                for (int in = 0; in < 4; in++) {
                    asm volatile(
                        "mma.sync.aligned.m16n8k8.row.col.f32.tf32.tf32.f32 "
                        "{%0,%1,%2,%3}, {%4,%5,%6,%7}, {%8,%9}, {%0,%1,%2,%3};"
                        : "+f"(acc[im][in][0]), "+f"(acc[im][in][1]),
                          "+f"(acc[im][in][2]), "+f"(acc[im][in][3])
                        : "r"(a[im][0]), "r"(a[im][1]), "r"(a[im][2]), "r"(a[im][3]),
                          "r"(b[in][0]), "r"(b[in][1]));
                }
        }

        if (havenext) {
            STORET(buf ^ 1);
            __syncthreads();
            buf ^= 1;
        }
    }

    // epilogue
#pragma unroll
    for (int im = 0; im < 2; im++) {
#pragma unroll
        for (int in = 0; in < 4; in++) {
            int Cc = wn + in * 8 + 2 * tig;
            if (Cc >= Nc) continue;
            float bx = bias[Cc], by = bias[Cc + 1];
            int R0 = row0 + wm + im * 16 + g;
            float v0 = acc[im][in][0] + bx;
            float v1 = acc[im][in][1] + by;
            float v2 = acc[im][in][2] + bx;
            float v3 = acc[im][in][3] + by;
            if (doRelu) {
                v0 = fmaxf(v0, 0.f); v1 = fmaxf(v1, 0.f);
                v2 = fmaxf(v2, 0.f); v3 = fmaxf(v3, 0.f);
            }
            if (R0 < M)
                *reinterpret_cast<float2*>(C + (size_t)R0 * ldc + Cc) = make_float2(v0, v1);
            if (R0 + 8 < M)
                *reinterpret_cast<float2*>(C + (size_t)(R0 + 8) * ldc + Cc) = make_float2(v2, v3);
        }
    }
#undef LOADT
#undef STORET
}

// ---------------------------------------------------------------------------
__global__ void k_stats() {
    int f = threadIdx.x & 63;
    int slot = threadIdx.x >> 6;
    float s = 0.f, s2 = 0.f;
    for (int i = blockIdx.x * 4 + slot; i < NN; i += gridDim.x * 4) {
        float v = g_z[(size_t)i * ZF + f];
        s += v;
        s2 += v * v;
    }
    __shared__ float sh[2][4][64];
    sh[0][slot][f] = s;
    sh[1][slot][f] = s2;
    __syncthreads();
    if (slot == 0) {
        float ts = sh[0][0][f] + sh[0][1][f] + sh[0][2][f] + sh[0][3][f];
        float t2 = sh[1][0][f] + sh[1][1][f] + sh[1][2][f] + sh[1][3][f];
        atomicAdd(g_sum + f, ts);
        atomicAdd(g_sumsq + f, t2);
    }
}

// BN finalize fused into apply: per-thread recompute of scale/shift (broadcast loads)
__global__ void k_bnapply(const float* __restrict__ gamma, const float* __restrict__ beta) {
    int i = blockIdx.x * blockDim.x + threadIdx.x;
    if (i >= NN * HF) return;
    int node = i >> 6, f = i & 63;
    float mu = g_sum[f] * (1.f / (float)NN);
    float var = g_sumsq[f] * (1.f / (float)NN) - mu * mu;
    float sc = gamma[f] * rsqrtf(var + 1e-5f);
    float sh = beta[f] - mu * sc;
    size_t idx = (size_t)node * ZF + f;
    g_z[idx] = g_z[idx] * sc + sh;
}

// ---------------------------------------------------------------------------
// SpMM: dst[u] = dinv[u] * sum_{v in adj(u)} dinv[v] * src[v]  (- diag2[u]*prev[u])
// HALF-WARP per node: 16 lanes x float4 = 64 features.
// ---------------------------------------------------------------------------
__global__ void k_spmm(int srcInZ, int srcOff, int prevMode, int prevOff,
                       int dstOff, int writeCur) {
    int node = blockIdx.x * 16 + (threadIdx.x >> 4);
    if (node >= NN) return;
    int l4 = (threadIdx.x & 15) * 4;

    const float* src = srcInZ ? (g_z + srcOff) : g_curB;
    int sld = srcInZ ? ZF : HF;

    int s = g_rowptr[node];
    int e = g_rowptr[node + 1];
    float ax = 0.f, ay = 0.f, az = 0.f, aw = 0.f;
#pragma unroll 4
    for (int j = s; j < e; j++) {
        int v = g_adj[j];
        float dv = g_dinv[v];
        float4 xv = *reinterpret_cast<const float4*>(src + (size_t)v * sld + l4);
        ax += dv * xv.x;
        ay += dv * xv.y;
        az += dv * xv.z;
        aw += dv * xv.w;
    }
    float du = g_dinv[node];
    ax *= du; ay *= du; az *= du; aw *= du;
    if (prevMode) {
        const float* prev = (prevMode == 1) ? (g_z + prevOff) : g_curB;
        int pld = (prevMode == 1) ? ZF : HF;
        float d2 = g_diag2[node];
        float4 p = *reinterpret_cast<const float4*>(prev + (size_t)node * pld + l4);
        ax -= d2 * p.x;
        ay -= d2 * p.y;
        az -= d2 * p.z;
        aw -= d2 * p.w;
    }
    *reinterpret_cast<float4*>(g_z + dstOff + (size_t)node * ZF + l4) =
        make_float4(ax, ay, az, aw);
    if (writeCur) {
        float4 sown = *reinterpret_cast<const float4*>(src + (size_t)node * sld + l4);
        *reinterpret_cast<float4*>(g_curB + (size_t)node * HF + l4) =
            make_float4(sown.x + ax, sown.y + ay, sown.z + az, sown.w + aw);
    }
}

// ---------------------------------------------------------------------------
extern "C" void kernel_launch(void* const* d_in, const int* in_sizes, int n_in,
                              void* d_out, int out_size) {
    const float* x       = (const float*)d_in[0];
    const int*   ei32    = (const int*)d_in[1];
    const float* W_embed = (const float*)d_in[2];
    const float* b_embed = (const float*)d_in[3];
    const float* bn_g    = (const float*)d_in[4];
    const float* bn_b    = (const float*)d_in[5];
    const float* W1      = (const float*)d_in[6];
    const float* b1      = (const float*)d_in[7];
    const float* W2      = (const float*)d_in[8];
    const float* b2      = (const float*)d_in[9];
    float* out = (float*)d_out;

    const int NPART = (NN + 255) / 256;  // 391
    int mma_grid = (NN + 127) / 128;

    // prep (dinv folded into scan1)
    k_init<<<256, 256>>>(ei32);
    k_deg<<<(EE + 255) / 256, 256>>>(ei32);
    k_scan1<<<NPART, 256>>>();
    k_scan2<<<1, 512>>>(NPART);
    k_scan3<<<NPART, 256>>>();

    // embed GEMM (independent of graph prep)
    k_mma<<<mma_grid, 256>>>(x, NN, INF_, INF_, W_embed, HF, INF_, b_embed,
                             nullptr, ZF, 1, /*aSel*/0, /*cSel*/1);

    // adjacency fill (needs dinv + rowptr)
    k_fill<<<(EE + 255) / 256, 256>>>(ei32);

    // batchnorm (training stats)
    k_stats<<<256, 256>>>();
    k_bnapply<<<(NN * HF + 255) / 256, 256>>>(bn_g, bn_b);

    int spmm_grid = (NN + 15) / 16;
    // hop 1
    k_spmm<<<spmm_grid, 256>>>(1, 0 * HF, 0, 0, 1 * HF, 0);
    k_spmm<<<spmm_grid, 256>>>(1, 1 * HF, 1, 0 * HF, 2 * HF, 1);
    // hop 2
    k_spmm<<<spmm_grid, 256>>>(0, 0, 0, 0, 3 * HF, 0);
    k_spmm<<<spmm_grid, 256>>>(1, 3 * HF, 2, 0, 4 * HF, 0);

    // MLP
    k_mma<<<mma_grid, 256>>>(nullptr, NN, ZF, ZF, W1, HF, ZF, b1,
                             nullptr, HF, 1, /*aSel*/1, /*cSel*/2);
    k_mma<<<mma_grid, 256>>>(nullptr, NN, HF, HF, W2, CF, HF, b2,
                             out, CF, 0, /*aSel*/2, /*cSel*/0);
}

// round 8
// speedup vs baseline: 2.1091x; 1.0728x over previous
#include <cuda_runtime.h>

// ---------------------------------------------------------------------------
// H2GCN forward. tf32 tensor-core GEMMs (3-stage cp.async pipeline, ldmatrix
// fragment loads, post-load tf32 cvt), parallel scan, half-warp SpMM.
// ---------------------------------------------------------------------------

#define NN   100000
#define EE   800000
#define INF_ 512
#define HF   64
#define CF   40
#define ZF   320   // 5 * HF concat width

// ---- scratch (static device globals; no allocation anywhere) ----
__device__ float g_deg[NN];
__device__ float g_dinv[NN];
__device__ float g_diag2[NN];
__device__ int   g_rowptr[NN + 1];
__device__ int   g_cursor[NN];
__device__ int   g_part[512];
__device__ int   g_adj[2 * EE];
__device__ float g_z[(size_t)NN * ZF];    // chunks: h,h1a,h2a,h1b,h2b
__device__ float g_curB[(size_t)NN * HF];
__device__ float g_hid[(size_t)NN * HF];
__device__ float g_sum[HF];
__device__ float g_sumsq[HF];
__device__ int   g_is64;

// ---------------------------------------------------------------------------
__device__ __forceinline__ void load_edge(const int* __restrict__ ei32, int e,
                                          int& u, int& v) {
    if (g_is64) {
        u = ei32[2 * e];
        v = ei32[2 * EE + 2 * e];
    } else {
        u = ei32[e];
        v = ei32[EE + e];
    }
}

// init + dtype probe (int64 LE values < 2^31 -> odd int32 words all zero)
__global__ void k_init(const int* __restrict__ ei32) {
    int i = blockIdx.x * blockDim.x + threadIdx.x;
    int stride = gridDim.x * blockDim.x;
    for (int j = i; j < NN; j += stride) {
        g_deg[j] = 0.f;
        g_diag2[j] = 0.f;
        g_cursor[j] = 0;
    }
    if (i < HF) { g_sum[i] = 0.f; g_sumsq[i] = 0.f; }
    if (i == 0) {
        int oddzero = 1;
#pragma unroll
        for (int q = 1; q < 16; q += 2)
            if (ei32[q] != 0) oddzero = 0;
        g_is64 = oddzero;
    }
}

__global__ void k_deg(const int* __restrict__ ei32) {
    int e = blockIdx.x * blockDim.x + threadIdx.x;
    if (e >= EE) return;
    int u, v;
    load_edge(ei32, e, u, v);
    if ((unsigned)u >= NN || (unsigned)v >= NN || u == v) return;
    atomicAdd(g_deg + u, 1.f);
    atomicAdd(g_deg + v, 1.f);
}

// ---- 3-phase exclusive scan of (int)g_deg -> g_rowptr; also emits dinv ----
__global__ void k_scan1() {
    __shared__ int sh[256];
    int t = threadIdx.x;
    int i = blockIdx.x * 256 + t;
    float d = (i < NN) ? g_deg[i] : 0.f;
    if (i < NN) g_dinv[i] = (d > 0.f) ? rsqrtf(d) : 0.f;
    sh[t] = (int)d;
    __syncthreads();
    for (int off = 128; off > 0; off >>= 1) {
        if (t < off) sh[t] += sh[t + off];
        __syncthreads();
    }
    if (t == 0) g_part[blockIdx.x] = sh[0];
}

__global__ void k_scan2(int np) {  // 1 block, 512 threads
    __shared__ int sh[512];
    int t = threadIdx.x;
    int v = (t < np) ? g_part[t] : 0;
    sh[t] = v;
    __syncthreads();
    for (int off = 1; off < 512; off <<= 1) {
        int x = (t >= off) ? sh[t - off] : 0;
        __syncthreads();
        sh[t] += x;
        __syncthreads();
    }
    if (t < np) g_part[t] = sh[t] - v;  // exclusive
    if (t == 511) g_rowptr[NN] = sh[511];
}

__global__ void k_scan3() {
    __shared__ int sh[256];
    int t = threadIdx.x;
    int i = blockIdx.x * 256 + t;
    int v = (i < NN) ? (int)g_deg[i] : 0;
    sh[t] = v;
    __syncthreads();
    for (int off = 1; off < 256; off <<= 1) {
        int x = (t >= off) ? sh[t - off] : 0;
        __syncthreads();
        sh[t] += x;
        __syncthreads();
    }
    if (i < NN) g_rowptr[i] = g_part[blockIdx.x] + sh[t] - v;
}

__global__ void k_fill(const int* __restrict__ ei32) {
    int e = blockIdx.x * blockDim.x + threadIdx.x;
    if (e >= EE) return;
    int u, v;
    load_edge(ei32, e, u, v);
    if ((unsigned)u >= NN || (unsigned)v >= NN || u == v) return;
    float w = g_dinv[u] * g_dinv[v];
    float ww = w * w;
    atomicAdd(g_diag2 + u, ww);
    atomicAdd(g_diag2 + v, ww);
    int p = atomicAdd(g_cursor + u, 1);
    g_adj[g_rowptr[u] + p] = v;
    int q = atomicAdd(g_cursor + v, 1);
    g_adj[g_rowptr[v] + q] = u;
}

// ---------------------------------------------------------------------------
// tf32 tensor-core GEMM, 3-stage cp.async pipeline + ldmatrix:
// C = act(A[MxK] @ B[NcxK]^T + bias). BM=128, BN=64, BK=16, 256 threads.
// ---------------------------------------------------------------------------
__device__ __forceinline__ unsigned f2tf(float f) {
    unsigned r;
    asm("cvt.rna.tf32.f32 %0, %1;" : "=r"(r) : "f"(f));
    return r;
}
__device__ __forceinline__ unsigned u2tf(unsigned u) {
    return f2tf(__uint_as_float(u));
}

#define SAS 20       // row stride (words): 80B rows -> conflict-free phases
#define STG 3        // pipeline stages
#define A_STG (128 * SAS)
#define B_STG (64 * SAS)

__device__ __forceinline__ void ldsm4(unsigned& r0, unsigned& r1,
                                      unsigned& r2, unsigned& r3, unsigned addr) {
    asm volatile("ldmatrix.sync.aligned.m8n8.x4.shared.b16 {%0,%1,%2,%3}, [%4];"
                 : "=r"(r0), "=r"(r1), "=r"(r2), "=r"(r3) : "r"(addr));
}

__global__ void k_mma(const float* __restrict__ Ain, int M, int K, int lda,
                      const float* __restrict__ B, int Nc, int ldb,
                      const float* __restrict__ bias,
                      float* __restrict__ Cout, int ldc, int doRelu,
                      int aSel, int cSel) {
    const float* A = (aSel == 1) ? g_z : (aSel == 2) ? g_hid : Ain;
    float* C = (cSel == 1) ? g_z : (cSel == 2) ? g_hid : Cout;

    __shared__ unsigned As[STG * A_STG];
    __shared__ unsigned Bs[STG * B_STG];

    int t = threadIdx.x;
    int w = t >> 5, lane = t & 31;
    int g = lane >> 2, tig = lane & 3;
    int wm = (w & 3) * 32;
    int wn = (w >> 2) * 32;
    int row0 = blockIdx.x * 128;

    float acc[2][4][4];
#pragma unroll
    for (int im = 0; im < 2; im++)
#pragma unroll
        for (int in = 0; in < 4; in++)
#pragma unroll
            for (int q = 0; q < 4; q++) acc[im][in][q] = 0.f;

    int ar = t >> 1, ac = t & 1;
    int br = t >> 2, bc4 = t & 3;
    int gr = row0 + ar;
    int pa = (gr < M) ? 16 : 0;
    int pb = (br < Nc) ? 16 : 0;
    const float* srcAbase = A + (size_t)(gr < M ? gr : M - 1) * lda + ac * 4;
    const float* srcBbase = B + (size_t)(br < Nc ? br : 0) * ldb + bc4 * 4;

    unsigned sa_A = (unsigned)__cvta_generic_to_shared(&As[0]);
    unsigned sa_B = (unsigned)__cvta_generic_to_shared(&Bs[0]);
    unsigned dstA0 = sa_A + (unsigned)(ar * SAS + ac * 4) * 4;
    unsigned dstB0 = sa_B + (unsigned)(br * SAS + bc4 * 4) * 4;

    // ldmatrix per-lane source offsets
    int lrow = lane & 7, lt = lane >> 3;
    int aoffw = (wm + (lt & 1) * 8 + lrow) * SAS + (lt >> 1) * 4;
    int boffw = (wn + (lt >> 1) * 8 + lrow) * SAS + (lt & 1) * 4;

#define ISSUE(st, k0)                                                          \
    {                                                                          \
        unsigned dA = dstA0 + (st) * (A_STG * 4);                              \
        const float* sA = srcAbase + (k0);                                     \
        asm volatile("cp.async.cg.shared.global [%0], [%1], 16, %2;"           \
                     :: "r"(dA), "l"(sA), "r"(pa));                            \
        asm volatile("cp.async.cg.shared.global [%0], [%1], 16, %2;"           \
                     :: "r"(dA + 32), "l"(sA + 8), "r"(pa));                   \
        unsigned dB = dstB0 + (st) * (B_STG * 4);                              \
        const float* sB = srcBbase + (k0);                                     \
        asm volatile("cp.async.cg.shared.global [%0], [%1], 16, %2;"           \
                     :: "r"(dB), "l"(sB), "r"(pb));                            \
    }

    int iters = K >> 4;
    ISSUE(0, 0);
    asm volatile("cp.async.commit_group;");
    ISSUE(1, 16);
    asm volatile("cp.async.commit_group;");

    int stage = 0;
    for (int i = 0; i < iters; i++) {
        asm volatile("cp.async.wait_group 1;");
        __syncthreads();

        int nx = i + 2;
        if (nx < iters) {
            int nst = nx % STG;
            ISSUE(nst, nx * 16);
        }
        asm volatile("cp.async.commit_group;");

        unsigned aB = sa_A + (unsigned)(stage * (A_STG * 4) + aoffw * 4);
        unsigned bB = sa_B + (unsigned)(stage * (B_STG * 4) + boffw * 4);

#pragma unroll
        for (int ks = 0; ks < 2; ks++) {
            unsigned kbb = ks * 32;
            unsigned a[2][4];
            ldsm4(a[0][0], a[0][1], a[0][2], a[0][3], aB + kbb);
            ldsm4(a[1][0], a[1][1], a[1][2], a[1][3], aB + kbb + 16 * SAS * 4);
            unsigned b[4][2];
            ldsm4(b[0][0], b[0][1], b[1][0], b[1][1], bB + kbb);
            ldsm4(b[2][0], b[2][1], b[3][0], b[3][1], bB + kbb + 16 * SAS * 4);
#pragma unroll
            for (int im = 0; im < 2; im++)
#pragma unroll
                for (int q = 0; q < 4; q++) a[im][q] = u2tf(a[im][q]);
#pragma unroll
            for (int in = 0; in < 4; in++) {
                b[in][0] = u2tf(b[in][0]);
                b[in][1] = u2tf(b[in][1]);
            }
#pragma unroll
            for (int im = 0; im < 2; im++)
#pragma unroll
                for (int in = 0; in < 4; in++) {
                    asm volatile(
                        "mma.sync.aligned.m16n8k8.row.col.f32.tf32.tf32.f32 "
                        "{%0,%1,%2,%3}, {%4,%5,%6,%7}, {%8,%9}, {%0,%1,%2,%3};"
                        : "+f"(acc[im][in][0]), "+f"(acc[im][in][1]),
                          "+f"(acc[im][in][2]), "+f"(acc[im][in][3])
                        : "r"(a[im][0]), "r"(a[im][1]), "r"(a[im][2]), "r"(a[im][3]),
                          "r"(b[in][0]), "r"(b[in][1]));
                }
        }
        stage = (stage + 1 == STG) ? 0 : stage + 1;
    }

    // epilogue
#pragma unroll
    for (int im = 0; im < 2; im++) {
#pragma unroll
        for (int in = 0; in < 4; in++) {
            int Cc = wn + in * 8 + 2 * tig;
            if (Cc >= Nc) continue;
            float bx = bias[Cc], by = bias[Cc + 1];
            int R0 = row0 + wm + im * 16 + g;
            float v0 = acc[im][in][0] + bx;
            float v1 = acc[im][in][1] + by;
            float v2 = acc[im][in][2] + bx;
            float v3 = acc[im][in][3] + by;
            if (doRelu) {
                v0 = fmaxf(v0, 0.f); v1 = fmaxf(v1, 0.f);
                v2 = fmaxf(v2, 0.f); v3 = fmaxf(v3, 0.f);
            }
            if (R0 < M)
                *reinterpret_cast<float2*>(C + (size_t)R0 * ldc + Cc) = make_float2(v0, v1);
            if (R0 + 8 < M)
                *reinterpret_cast<float2*>(C + (size_t)(R0 + 8) * ldc + Cc) = make_float2(v2, v3);
        }
    }
#undef ISSUE
}

// ---------------------------------------------------------------------------
__global__ void k_stats() {
    int f = threadIdx.x & 63;
    int slot = threadIdx.x >> 6;
    float s = 0.f, s2 = 0.f;
    for (int i = blockIdx.x * 4 + slot; i < NN; i += gridDim.x * 4) {
        float v = g_z[(size_t)i * ZF + f];
        s += v;
        s2 += v * v;
    }
    __shared__ float sh[2][4][64];
    sh[0][slot][f] = s;
    sh[1][slot][f] = s2;
    __syncthreads();
    if (slot == 0) {
        float ts = sh[0][0][f] + sh[0][1][f] + sh[0][2][f] + sh[0][3][f];
        float t2 = sh[1][0][f] + sh[1][1][f] + sh[1][2][f] + sh[1][3][f];
        atomicAdd(g_sum + f, ts);
        atomicAdd(g_sumsq + f, t2);
    }
}

// BN finalize fused into apply
__global__ void k_bnapply(const float* __restrict__ gamma, const float* __restrict__ beta) {
    int i = blockIdx.x * blockDim.x + threadIdx.x;
    if (i >= NN * HF) return;
    int node = i >> 6, f = i & 63;
    float mu = g_sum[f] * (1.f / (float)NN);
    float var = g_sumsq[f] * (1.f / (float)NN) - mu * mu;
    float sc = gamma[f] * rsqrtf(var + 1e-5f);
    float sh = beta[f] - mu * sc;
    size_t idx = (size_t)node * ZF + f;
    g_z[idx] = g_z[idx] * sc + sh;
}

// ---------------------------------------------------------------------------
// SpMM: half-warp per node, 16 lanes x float4.
// ---------------------------------------------------------------------------
__global__ void k_spmm(int srcInZ, int srcOff, int prevMode, int prevOff,
                       int dstOff, int writeCur) {
    int node = blockIdx.x * 16 + (threadIdx.x >> 4);
    if (node >= NN) return;
    int l4 = (threadIdx.x & 15) * 4;

    const float* src = srcInZ ? (g_z + srcOff) : g_curB;
    int sld = srcInZ ? ZF : HF;

    int s = g_rowptr[node];
    int e = g_rowptr[node + 1];
    float ax = 0.f, ay = 0.f, az = 0.f, aw = 0.f;
#pragma unroll 4
    for (int j = s; j < e; j++) {
        int v = g_adj[j];
        float dv = g_dinv[v];
        float4 xv = *reinterpret_cast<const float4*>(src + (size_t)v * sld + l4);
        ax += dv * xv.x;
        ay += dv * xv.y;
        az += dv * xv.z;
        aw += dv * xv.w;
    }
    float du = g_dinv[node];
    ax *= du; ay *= du; az *= du; aw *= du;
    if (prevMode) {
        const float* prev = (prevMode == 1) ? (g_z + prevOff) : g_curB;
        int pld = (prevMode == 1) ? ZF : HF;
        float d2 = g_diag2[node];
        float4 p = *reinterpret_cast<const float4*>(prev + (size_t)node * pld + l4);
        ax -= d2 * p.x;
        ay -= d2 * p.y;
        az -= d2 * p.z;
        aw -= d2 * p.w;
    }
    *reinterpret_cast<float4*>(g_z + dstOff + (size_t)node * ZF + l4) =
        make_float4(ax, ay, az, aw);
    if (writeCur) {
        float4 sown = *reinterpret_cast<const float4*>(src + (size_t)node * sld + l4);
        *reinterpret_cast<float4*>(g_curB + (size_t)node * HF + l4) =
            make_float4(sown.x + ax, sown.y + ay, sown.z + az, sown.w + aw);
    }
}

// ---------------------------------------------------------------------------
extern "C" void kernel_launch(void* const* d_in, const int* in_sizes, int n_in,
                              void* d_out, int out_size) {
    const float* x       = (const float*)d_in[0];
    const int*   ei32    = (const int*)d_in[1];
    const float* W_embed = (const float*)d_in[2];
    const float* b_embed = (const float*)d_in[3];
    const float* bn_g    = (const float*)d_in[4];
    const float* bn_b    = (const float*)d_in[5];
    const float* W1      = (const float*)d_in[6];
    const float* b1      = (const float*)d_in[7];
    const float* W2      = (const float*)d_in[8];
    const float* b2      = (const float*)d_in[9];
    float* out = (float*)d_out;

    const int NPART = (NN + 255) / 256;  // 391
    int mma_grid = (NN + 127) / 128;

    // prep (dinv folded into scan1)
    k_init<<<256, 256>>>(ei32);
    k_deg<<<(EE + 255) / 256, 256>>>(ei32);
    k_scan1<<<NPART, 256>>>();
    k_scan2<<<1, 512>>>(NPART);
    k_scan3<<<NPART, 256>>>();

    // embed GEMM (independent of graph prep)
    k_mma<<<mma_grid, 256>>>(x, NN, INF_, INF_, W_embed, HF, INF_, b_embed,
                             nullptr, ZF, 1, /*aSel*/0, /*cSel*/1);

    // adjacency fill (needs dinv + rowptr)
    k_fill<<<(EE + 255) / 256, 256>>>(ei32);

    // batchnorm (training stats)
    k_stats<<<256, 256>>>();
    k_bnapply<<<(NN * HF + 255) / 256, 256>>>(bn_g, bn_b);

    int spmm_grid = (NN + 15) / 16;
    // hop 1
    k_spmm<<<spmm_grid, 256>>>(1, 0 * HF, 0, 0, 1 * HF, 0);
    k_spmm<<<spmm_grid, 256>>>(1, 1 * HF, 1, 0 * HF, 2 * HF, 1);
    // hop 2
    k_spmm<<<spmm_grid, 256>>>(0, 0, 0, 0, 3 * HF, 0);
    k_spmm<<<spmm_grid, 256>>>(1, 3 * HF, 2, 0, 4 * HF, 0);

    // MLP
    k_mma<<<mma_grid, 256>>>(nullptr, NN, ZF, ZF, W1, HF, ZF, b1,
                             nullptr, HF, 1, /*aSel*/1, /*cSel*/2);
    k_mma<<<mma_grid, 256>>>(nullptr, NN, HF, HF, W2, CF, HF, b2,
                             out, CF, 0, /*aSel*/2, /*cSel*/0);
}